// round 4
// baseline (speedup 1.0000x reference)
#include <cuda_runtime.h>
#include <math.h>

// Problem constants
#define TT 256   // T (time steps)
#define BB 128   // batch
#define SS 512   // memory sequence length
#define DD 256   // EMBED = HID = ENC = DEC
#define GG 1024  // 4*HID gates

// ---------------- scratch (__device__ globals; no allocation allowed) ----------------
__device__ float g_memproj[BB * SS * DD];  // [b][s][d] : 67 MB
__device__ float g_h[BB * DD];
__device__ float g_c[BB * DD];
__device__ float g_ctx[BB * DD];
__device__ float g_gates[BB * GG];

// ---------------- fast math (MUFU-based, ~1e-6 rel err) ----------------
__device__ __forceinline__ float fast_tanh(float x) {
    x = fminf(fmaxf(x, -15.f), 15.f);
    float e = __expf(2.f * x);                 // EX2-based
    return __fdividef(e - 1.f, e + 1.f);       // RCP-based
}
__device__ __forceinline__ float fast_sigmoid(float x) {
    return __fdividef(1.f, 1.f + __expf(-x));  // saturates correctly at +/-inf
}

// ---------------- init: zero h, c, out[0] ----------------
__global__ void k_init(float* __restrict__ out0) {
    int idx = blockIdx.x * blockDim.x + threadIdx.x;  // 0..32767
    g_h[idx] = 0.f;
    g_c[idx] = 0.f;
    out0[idx] = 0.f;
}

// ---------------- prologue GEMM: g_memproj[b,s,d] = sum_e memory[s,b,e] * W_attn[d,256+e] + b_attn[d]
// M = B*S = 65536 rows (r = b*512+s), N = 256, K = 256. BM=64 BN=64 BK=32, 256 thr, 4x4/thread.
__global__ __launch_bounds__(256) void k_memproj(const float* __restrict__ memory,
                                                 const float* __restrict__ W_attn,
                                                 const float* __restrict__ b_attn) {
    __shared__ float Ash[32][68];  // [k][m], padded, float4-aligned rows
    __shared__ float Bsh[32][68];  // [k][n]
    int tid = threadIdx.x;
    int tx = tid & 15, ty = tid >> 4;
    int n0 = blockIdx.x * 64;   // d tile
    int m0 = blockIdx.y * 64;   // row tile

    float acc[4][4];
#pragma unroll
    for (int i = 0; i < 4; i++)
#pragma unroll
        for (int j = 0; j < 4; j++) acc[i][j] = 0.f;

    for (int k0 = 0; k0 < DD; k0 += 32) {
#pragma unroll
        for (int i = 0; i < 8; i++) {
            int idx = tid + i * 256;           // 0..2047
            int e = idx & 31;
            int m = idx >> 5;
            int r = m0 + m;
            int b = r >> 9;                    // /512
            int s = r & 511;
            Ash[e][m] = memory[((size_t)(s * BB + b)) * DD + k0 + e];
            int d = m;                         // same decomposition for B tile
            Bsh[e][d] = W_attn[(size_t)(n0 + d) * (2 * DD) + DD + k0 + e];
        }
        __syncthreads();
#pragma unroll
        for (int k = 0; k < 32; k++) {
            float4 a = *(const float4*)&Ash[k][ty * 4];
            float4 bv = *(const float4*)&Bsh[k][tx * 4];
            float av[4] = {a.x, a.y, a.z, a.w};
            float bw[4] = {bv.x, bv.y, bv.z, bv.w};
#pragma unroll
            for (int i = 0; i < 4; i++)
#pragma unroll
                for (int j = 0; j < 4; j++) acc[i][j] = fmaf(av[i], bw[j], acc[i][j]);
        }
        __syncthreads();
    }
    float4 bias = *(const float4*)&b_attn[n0 + tx * 4];
#pragma unroll
    for (int i = 0; i < 4; i++) {
        int r = m0 + ty * 4 + i;
        float4 o;
        o.x = acc[i][0] + bias.x;
        o.y = acc[i][1] + bias.y;
        o.z = acc[i][2] + bias.z;
        o.w = acc[i][3] + bias.w;
        *(float4*)&g_memproj[(size_t)r * DD + n0 + tx * 4] = o;
    }
}

// ---------------- per-step attention: one block per batch element ----------------
// computes hWh = h @ W_h^T, energy sum+tanh, softmax over s, ctx = attn @ mem_bt
__global__ __launch_bounds__(512) void k_attn(const float* __restrict__ memory,
                                              const float* __restrict__ W_attn) {
    __shared__ float sh_h[DD];
    __shared__ float sh_w[DD];    // hWh
    __shared__ float sh_e[SS];    // e_sum -> attn weights
    __shared__ float sh_red[16];
    __shared__ float sh_sum[16];
    __shared__ float sh_p[512];

    int b = blockIdx.x;
    int tid = threadIdx.x;
    int lane = tid & 31;
    int warp = tid >> 5;  // 16 warps

    if (tid < DD) sh_h[tid] = g_h[b * DD + tid];
    __syncthreads();

    // hWh[d] = sum_k h[k] * W_attn[d, k]   (warp w handles d = w*16..w*16+15)
    for (int dd = 0; dd < 16; dd++) {
        int d = warp * 16 + dd;
        const float* wr = &W_attn[(size_t)d * (2 * DD)];
        float acc = 0.f;
#pragma unroll
        for (int j = 0; j < 8; j++) {
            int k = lane + j * 32;
            acc = fmaf(wr[k], sh_h[k], acc);
        }
#pragma unroll
        for (int o = 16; o; o >>= 1) acc += __shfl_xor_sync(0xffffffffu, acc, o);
        if (lane == 0) sh_w[d] = acc;
    }
    __syncthreads();

    // energy: e_sum[s] = sum_d tanh(mem_proj[b,s,d] + hWh[d]); warp per s
    for (int it = 0; it < 32; it++) {
        int s = warp + it * 16;
        const float* mp = &g_memproj[((size_t)(b * SS + s)) * DD];
        float acc = 0.f;
#pragma unroll
        for (int j = 0; j < 8; j++) {
            int d = lane + j * 32;
            acc += fast_tanh(mp[d] + sh_w[d]);
        }
#pragma unroll
        for (int o = 16; o; o >>= 1) acc += __shfl_xor_sync(0xffffffffu, acc, o);
        if (lane == 0) sh_e[s] = acc;
    }
    __syncthreads();

    // softmax over s (512 values, 512 threads: one each)
    float m = sh_e[tid];
#pragma unroll
    for (int o = 16; o; o >>= 1) m = fmaxf(m, __shfl_xor_sync(0xffffffffu, m, o));
    if (lane == 0) sh_red[warp] = m;
    __syncthreads();
    float mx = sh_red[0];
#pragma unroll
    for (int i = 1; i < 16; i++) mx = fmaxf(mx, sh_red[i]);
    float w = __expf(sh_e[tid] - mx);
    float ws = w;
#pragma unroll
    for (int o = 16; o; o >>= 1) ws += __shfl_xor_sync(0xffffffffu, ws, o);
    if (lane == 0) sh_sum[warp] = ws;
    __syncthreads();
    float total = 0.f;
#pragma unroll
    for (int i = 0; i < 16; i++) total += sh_sum[i];
    float inv = __fdividef(1.f, total);
    sh_e[tid] = w * inv;   // each thread only touches its own slot
    __syncthreads();

    // ctx[e] = sum_s attn[s] * memory[s,b,e]; thread = (e, s-parity), 8-way MLP unroll
    {
        int e = tid & 255;
        int sp = tid >> 8;  // 0 or 1
        const float* mb = memory + (size_t)b * DD + e;
        float a0 = 0.f, a1 = 0.f, a2 = 0.f, a3 = 0.f, a4 = 0.f, a5 = 0.f, a6 = 0.f, a7 = 0.f;
        for (int s = sp; s < SS; s += 16) {
            a0 = fmaf(sh_e[s],      mb[(size_t)(s)      * BB * DD], a0);
            a1 = fmaf(sh_e[s + 2],  mb[(size_t)(s + 2)  * BB * DD], a1);
            a2 = fmaf(sh_e[s + 4],  mb[(size_t)(s + 4)  * BB * DD], a2);
            a3 = fmaf(sh_e[s + 6],  mb[(size_t)(s + 6)  * BB * DD], a3);
            a4 = fmaf(sh_e[s + 8],  mb[(size_t)(s + 8)  * BB * DD], a4);
            a5 = fmaf(sh_e[s + 10], mb[(size_t)(s + 10) * BB * DD], a5);
            a6 = fmaf(sh_e[s + 12], mb[(size_t)(s + 12) * BB * DD], a6);
            a7 = fmaf(sh_e[s + 14], mb[(size_t)(s + 14) * BB * DD], a7);
        }
        sh_p[tid] = ((a0 + a1) + (a2 + a3)) + ((a4 + a5) + (a6 + a7));
    }
    __syncthreads();
    if (tid < DD) g_ctx[b * DD + tid] = sh_p[tid] + sh_p[tid + DD];
}

// ---------------- per-step gate GEMM ----------------
// gates[b, j] = sum_k A[b,k] * W[j,k] + b_ih[j] + b_hh[j]
// A = [tgt_t (256) | ctx (256) | h (256)],  W = [W_ih (512 cols) | W_hh (256 cols)]
// M=128, N=1024, K=768. BM=32 BN=32 BK=32, grid (32,4), 256 thr, 2x2/thread.
__global__ __launch_bounds__(256) void k_gemm(const float* __restrict__ tgt_t,
                                              const float* __restrict__ W_ih,
                                              const float* __restrict__ W_hh,
                                              const float* __restrict__ b_ih,
                                              const float* __restrict__ b_hh) {
    __shared__ float Ash[32][34];  // [k][m]
    __shared__ float Bsh[32][34];  // [k][j]
    int tid = threadIdx.x;
    int tx = tid & 15, ty = tid >> 4;
    int n0 = blockIdx.x * 32;   // gate tile
    int m0 = blockIdx.y * 32;   // batch tile

    float acc[2][2];
    acc[0][0] = acc[0][1] = acc[1][0] = acc[1][1] = 0.f;

    for (int k0 = 0; k0 < 768; k0 += 32) {
        const float* srcA;
        int koff;
        if (k0 < 256)      { srcA = tgt_t;  koff = k0; }
        else if (k0 < 512) { srcA = g_ctx;  koff = k0 - 256; }
        else               { srcA = g_h;    koff = k0 - 512; }
#pragma unroll
        for (int i = 0; i < 4; i++) {
            int idx = tid + i * 256;        // 0..1023
            int k = idx & 31;
            int m = idx >> 5;
            Ash[k][m] = srcA[(m0 + m) * DD + koff + k];
            int j = m;
            float wv;
            if (k0 < 512) wv = W_ih[(size_t)(n0 + j) * 512 + k0 + k];
            else          wv = W_hh[(size_t)(n0 + j) * 256 + (k0 - 512) + k];
            Bsh[k][j] = wv;
        }
        __syncthreads();
#pragma unroll
        for (int k = 0; k < 32; k++) {
            float2 a = *(const float2*)&Ash[k][ty * 2];
            float2 bv = *(const float2*)&Bsh[k][tx * 2];
            acc[0][0] = fmaf(a.x, bv.x, acc[0][0]);
            acc[0][1] = fmaf(a.x, bv.y, acc[0][1]);
            acc[1][0] = fmaf(a.y, bv.x, acc[1][0]);
            acc[1][1] = fmaf(a.y, bv.y, acc[1][1]);
        }
        __syncthreads();
    }
    int col = n0 + tx * 2;
    float bias0 = b_ih[col] + b_hh[col];
    float bias1 = b_ih[col + 1] + b_hh[col + 1];
#pragma unroll
    for (int i = 0; i < 2; i++) {
        int b = m0 + ty * 2 + i;
        float2 o = make_float2(acc[i][0] + bias0, acc[i][1] + bias1);
        *(float2*)&g_gates[(size_t)b * GG + col] = o;
    }
}

// ---------------- per-step LSTM cell ----------------
__global__ __launch_bounds__(256) void k_cell(float* __restrict__ out_t) {
    int idx = blockIdx.x * blockDim.x + threadIdx.x;  // 0..32767
    int b = idx >> 8;
    int hd = idx & 255;
    const float* g = &g_gates[(size_t)b * GG];
    float gi = fast_sigmoid(g[hd]);
    float gf = fast_sigmoid(g[hd + 256]);
    float gc = fast_tanh(g[hd + 512]);
    float go = fast_sigmoid(g[hd + 768]);
    float c = gf * g_c[idx] + gi * gc;
    float h = go * fast_tanh(c);
    g_c[idx] = c;
    g_h[idx] = h;
    out_t[idx] = h;
}

// ---------------- launch ----------------
extern "C" void kernel_launch(void* const* d_in, const int* in_sizes, int n_in,
                              void* d_out, int out_size) {
    const float* tgt    = (const float*)d_in[0];  // (T,B,256)
    const float* memory = (const float*)d_in[1];  // (S,B,256)
    const float* W_attn = (const float*)d_in[2];  // (256,512)
    const float* b_attn = (const float*)d_in[3];  // (256,)
    const float* W_ih   = (const float*)d_in[4];  // (1024,512)
    const float* W_hh   = (const float*)d_in[5];  // (1024,256)
    const float* b_ih   = (const float*)d_in[6];  // (1024,)
    const float* b_hh   = (const float*)d_in[7];  // (1024,)
    float* out = (float*)d_out;                   // (T,B,256)

    (void)in_sizes; (void)n_in; (void)out_size;

    k_init<<<128, 256>>>(out);                    // h=c=0, out[0]=0

    dim3 gmp(4, 1024);
    k_memproj<<<gmp, 256>>>(memory, W_attn, b_attn);

    for (int t = 1; t < TT; t++) {
        k_attn<<<BB, 512>>>(memory, W_attn);
        dim3 gg(32, 4);
        k_gemm<<<gg, 256>>>(tgt + (size_t)t * BB * DD, W_ih, W_hh, b_ih, b_hh);
        k_cell<<<128, 256>>>(out + (size_t)t * BB * DD);
    }
}

// round 7
// speedup vs baseline: 1.1487x; 1.1487x over previous
#include <cuda_runtime.h>
#include <cuda_fp16.h>
#include <math.h>

// Problem constants
#define TT 256   // T (time steps)
#define BB 128   // batch
#define SS 512   // memory sequence length
#define DD 256   // EMBED = HID = ENC = DEC
#define GG 1024  // 4*HID gates

// ---------------- scratch (__device__ globals; no allocation allowed) ----------------
__device__ float g_memproj[BB * SS * DD];   // [b][s][d] fp32 : 67 MB
__device__ __half g_memt[BB * SS * DD];     // [b][s][e] fp16 : 34 MB
__device__ float g_h[BB * DD];
__device__ float g_c[BB * DD];
__device__ float g_ctx[BB * DD];
__device__ float g_gp[3][BB * GG];          // split-K gate partials

// ---------------- fast math (MUFU-based, ~1e-6 rel err) ----------------
__device__ __forceinline__ float fast_tanh(float x) {
    x = fminf(fmaxf(x, -15.f), 15.f);
    float e = __expf(2.f * x);
    return __fdividef(e - 1.f, e + 1.f);
}
__device__ __forceinline__ float fast_sigmoid(float x) {
    return __fdividef(1.f, 1.f + __expf(-x));
}

// ---------------- init: zero h, c, out[0] ----------------
__global__ void k_init(float* __restrict__ out0) {
    int idx = blockIdx.x * blockDim.x + threadIdx.x;  // 0..32767
    g_h[idx] = 0.f;
    g_c[idx] = 0.f;
    out0[idx] = 0.f;
}

// ---------------- one-time transpose: memt[b][s][e] = fp16(memory[s][b][e]) ----------------
__global__ __launch_bounds__(256) void k_tr(const float* __restrict__ memory) {
    int b = blockIdx.x;
    int tid = threadIdx.x;
#pragma unroll
    for (int i = 0; i < 16; i++) {
        int s = blockIdx.y * 16 + i;
        g_memt[(size_t)b * SS * DD + (size_t)s * DD + tid] =
            __float2half(memory[((size_t)s * BB + b) * DD + tid]);
    }
}

// ---------------- prologue GEMM: g_memproj[b,s,d] = sum_e memory[s,b,e] * W_attn[d,256+e] + b_attn[d]
__global__ __launch_bounds__(256) void k_memproj(const float* __restrict__ memory,
                                                 const float* __restrict__ W_attn,
                                                 const float* __restrict__ b_attn) {
    __shared__ __align__(16) float Ash[32][68];
    __shared__ __align__(16) float Bsh[32][68];
    int tid = threadIdx.x;
    int tx = tid & 15, ty = tid >> 4;
    int n0 = blockIdx.x * 64;
    int m0 = blockIdx.y * 64;

    float acc[4][4];
#pragma unroll
    for (int i = 0; i < 4; i++)
#pragma unroll
        for (int j = 0; j < 4; j++) acc[i][j] = 0.f;

    for (int k0 = 0; k0 < DD; k0 += 32) {
#pragma unroll
        for (int i = 0; i < 8; i++) {
            int idx = tid + i * 256;
            int e = idx & 31;
            int m = idx >> 5;
            int r = m0 + m;
            int b = r >> 9;
            int s = r & 511;
            Ash[e][m] = memory[((size_t)(s * BB + b)) * DD + k0 + e];
            int d = m;
            Bsh[e][d] = W_attn[(size_t)(n0 + d) * (2 * DD) + DD + k0 + e];
        }
        __syncthreads();
#pragma unroll
        for (int k = 0; k < 32; k++) {
            float4 a = *(const float4*)&Ash[k][ty * 4];
            float4 bv = *(const float4*)&Bsh[k][tx * 4];
            float av[4] = {a.x, a.y, a.z, a.w};
            float bw[4] = {bv.x, bv.y, bv.z, bv.w};
#pragma unroll
            for (int i = 0; i < 4; i++)
#pragma unroll
                for (int j = 0; j < 4; j++) acc[i][j] = fmaf(av[i], bw[j], acc[i][j]);
        }
        __syncthreads();
    }
    float4 bias = *(const float4*)&b_attn[n0 + tx * 4];
#pragma unroll
    for (int i = 0; i < 4; i++) {
        int r = m0 + ty * 4 + i;
        float4 o;
        o.x = acc[i][0] + bias.x;
        o.y = acc[i][1] + bias.y;
        o.z = acc[i][2] + bias.z;
        o.w = acc[i][3] + bias.w;
        *(float4*)&g_memproj[(size_t)r * DD + n0 + tx * 4] = o;
    }
}

// ---------------- per-step attention: one block per batch element ----------------
__global__ __launch_bounds__(512) void k_attn(const float* __restrict__ W_attn) {
    __shared__ __align__(16) float sh_h[DD];
    __shared__ __align__(16) float sh_w[DD];     // hWh
    __shared__ __align__(16) float sh_e[SS];     // e_sum -> attn weights
    __shared__ float sh_red[16];
    __shared__ float sh_sum[16];
    __shared__ __align__(16) float sh_ctxp[16][264];  // ctx partials per s-parity

    int b = blockIdx.x;
    int tid = threadIdx.x;
    int lane = tid & 31;
    int warp = tid >> 5;  // 16 warps

    if (tid < DD) sh_h[tid] = g_h[b * DD + tid];
    __syncthreads();

    // hWh[d] = sum_k h[k] * W_attn[d, k]  (warp w handles d = w*16..w*16+15)
    for (int dd = 0; dd < 16; dd++) {
        int d = warp * 16 + dd;
        const float* wr = &W_attn[(size_t)d * (2 * DD)];
        float acc = 0.f;
#pragma unroll
        for (int j = 0; j < 8; j++) {
            int k = lane + j * 32;
            acc = fmaf(wr[k], sh_h[k], acc);
        }
#pragma unroll
        for (int o = 16; o; o >>= 1) acc += __shfl_xor_sync(0xffffffffu, acc, o);
        if (lane == 0) sh_w[d] = acc;
    }
    __syncthreads();

    // energy: e_sum[s] = sum_d tanh(mem_proj[b,s,d] + hWh[d]); warp per s, float4 loads
    {
        const float4* wv = (const float4*)sh_w;
        float4 w0 = wv[lane];
        float4 w1 = wv[lane + 32];
#pragma unroll 2
        for (int it = 0; it < 32; it++) {
            int s = warp + it * 16;
            const float4* mp = (const float4*)&g_memproj[((size_t)(b * SS + s)) * DD];
            float4 a0 = mp[lane];
            float4 a1 = mp[lane + 32];
            float acc = fast_tanh(a0.x + w0.x) + fast_tanh(a0.y + w0.y) +
                        fast_tanh(a0.z + w0.z) + fast_tanh(a0.w + w0.w) +
                        fast_tanh(a1.x + w1.x) + fast_tanh(a1.y + w1.y) +
                        fast_tanh(a1.z + w1.z) + fast_tanh(a1.w + w1.w);
#pragma unroll
            for (int o = 16; o; o >>= 1) acc += __shfl_xor_sync(0xffffffffu, acc, o);
            if (lane == 0) sh_e[s] = acc;
        }
    }
    __syncthreads();

    // softmax over s (512 values, 512 threads)
    float m = sh_e[tid];
#pragma unroll
    for (int o = 16; o; o >>= 1) m = fmaxf(m, __shfl_xor_sync(0xffffffffu, m, o));
    if (lane == 0) sh_red[warp] = m;
    __syncthreads();
    float mx = sh_red[0];
#pragma unroll
    for (int i = 1; i < 16; i++) mx = fmaxf(mx, sh_red[i]);
    float w = __expf(sh_e[tid] - mx);
    float ws = w;
#pragma unroll
    for (int o = 16; o; o >>= 1) ws += __shfl_xor_sync(0xffffffffu, ws, o);
    if (lane == 0) sh_sum[warp] = ws;
    __syncthreads();
    float total = 0.f;
#pragma unroll
    for (int i = 0; i < 16; i++) total += sh_sum[i];
    float inv = __fdividef(1.f, total);
    sh_e[tid] = w * inv;
    __syncthreads();

    // ctx[e] = sum_s attn[s] * memt[b][s][e]; uint4 = 8 fp16 per thread-load
    {
        int e8 = tid & 31;   // e block of 8
        int sp = tid >> 5;   // s parity 0..15
        const uint4* mb = (const uint4*)(g_memt + (size_t)b * SS * DD);
        float acc[8];
#pragma unroll
        for (int j = 0; j < 8; j++) acc[j] = 0.f;
#pragma unroll 4
        for (int s = sp; s < SS; s += 16) {
            uint4 v = mb[s * 32 + e8];
            float a = sh_e[s];
            float2 f0 = __half22float2(*(__half2*)&v.x);
            float2 f1 = __half22float2(*(__half2*)&v.y);
            float2 f2 = __half22float2(*(__half2*)&v.z);
            float2 f3 = __half22float2(*(__half2*)&v.w);
            acc[0] = fmaf(a, f0.x, acc[0]);
            acc[1] = fmaf(a, f0.y, acc[1]);
            acc[2] = fmaf(a, f1.x, acc[2]);
            acc[3] = fmaf(a, f1.y, acc[3]);
            acc[4] = fmaf(a, f2.x, acc[4]);
            acc[5] = fmaf(a, f2.y, acc[5]);
            acc[6] = fmaf(a, f3.x, acc[6]);
            acc[7] = fmaf(a, f3.y, acc[7]);
        }
#pragma unroll
        for (int j = 0; j < 8; j++) sh_ctxp[sp][e8 * 8 + j] = acc[j];
    }
    __syncthreads();
    if (tid < DD) {
        float s = 0.f;
#pragma unroll
        for (int i = 0; i < 16; i++) s += sh_ctxp[i][tid];
        g_ctx[b * DD + tid] = s;
    }
}

// ---------------- per-step gate GEMM, split-K x3 ----------------
// kz=0: tgt_t x W_ih[:, 0:256]; kz=1: ctx x W_ih[:, 256:512]; kz=2: h x W_hh
__global__ __launch_bounds__(256) void k_gemm(const float* __restrict__ tgt_t,
                                              const float* __restrict__ W_ih,
                                              const float* __restrict__ W_hh) {
    __shared__ __align__(16) float Ash[32][34];
    __shared__ __align__(16) float Bsh[32][34];
    int tid = threadIdx.x;
    int tx = tid & 15, ty = tid >> 4;
    int n0 = blockIdx.x * 32;
    int m0 = blockIdx.y * 32;
    int kz = blockIdx.z;

    const float* A;
    const float* W;
    int ldw, col0;
    if (kz == 0)      { A = tgt_t; W = W_ih; ldw = 512; col0 = 0; }
    else if (kz == 1) { A = g_ctx; W = W_ih; ldw = 512; col0 = 256; }
    else              { A = g_h;   W = W_hh; ldw = 256; col0 = 0; }

    float acc[2][2];
    acc[0][0] = acc[0][1] = acc[1][0] = acc[1][1] = 0.f;

    for (int k0 = 0; k0 < 256; k0 += 32) {
#pragma unroll
        for (int i = 0; i < 4; i++) {
            int idx = tid + i * 256;
            int k = idx & 31;
            int m = idx >> 5;
            Ash[k][m] = A[(m0 + m) * DD + k0 + k];
            int j = m;
            Bsh[k][j] = W[(size_t)(n0 + j) * ldw + col0 + k0 + k];
        }
        __syncthreads();
#pragma unroll
        for (int k = 0; k < 32; k++) {
            float2 a = *(const float2*)&Ash[k][ty * 2];
            float2 bv = *(const float2*)&Bsh[k][tx * 2];
            acc[0][0] = fmaf(a.x, bv.x, acc[0][0]);
            acc[0][1] = fmaf(a.x, bv.y, acc[0][1]);
            acc[1][0] = fmaf(a.y, bv.x, acc[1][0]);
            acc[1][1] = fmaf(a.y, bv.y, acc[1][1]);
        }
        __syncthreads();
    }
    int col = n0 + tx * 2;
#pragma unroll
    for (int i = 0; i < 2; i++) {
        int b = m0 + ty * 2 + i;
        float2 o = make_float2(acc[i][0], acc[i][1]);
        *(float2*)&g_gp[kz][(size_t)b * GG + col] = o;
    }
}

// ---------------- per-step LSTM cell (sums split-K partials + bias) ----------------
__global__ __launch_bounds__(256) void k_cell(const float* __restrict__ b_ih,
                                              const float* __restrict__ b_hh,
                                              float* __restrict__ out_t) {
    int idx = blockIdx.x * blockDim.x + threadIdx.x;  // 0..32767
    int b = idx >> 8;
    int hd = idx & 255;
    size_t base = (size_t)b * GG;

    float vi = g_gp[0][base + hd] + g_gp[1][base + hd] + g_gp[2][base + hd]
             + b_ih[hd] + b_hh[hd];
    float vf = g_gp[0][base + hd + 256] + g_gp[1][base + hd + 256] + g_gp[2][base + hd + 256]
             + b_ih[hd + 256] + b_hh[hd + 256];
    float vg = g_gp[0][base + hd + 512] + g_gp[1][base + hd + 512] + g_gp[2][base + hd + 512]
             + b_ih[hd + 512] + b_hh[hd + 512];
    float vo = g_gp[0][base + hd + 768] + g_gp[1][base + hd + 768] + g_gp[2][base + hd + 768]
             + b_ih[hd + 768] + b_hh[hd + 768];

    float gi = fast_sigmoid(vi);
    float gf = fast_sigmoid(vf);
    float gc = fast_tanh(vg);
    float go = fast_sigmoid(vo);
    float c = gf * g_c[idx] + gi * gc;
    float h = go * fast_tanh(c);
    g_c[idx] = c;
    g_h[idx] = h;
    out_t[idx] = h;
}

// ---------------- launch ----------------
extern "C" void kernel_launch(void* const* d_in, const int* in_sizes, int n_in,
                              void* d_out, int out_size) {
    const float* tgt    = (const float*)d_in[0];  // (T,B,256)
    const float* memory = (const float*)d_in[1];  // (S,B,256)
    const float* W_attn = (const float*)d_in[2];  // (256,512)
    const float* b_attn = (const float*)d_in[3];  // (256,)
    const float* W_ih   = (const float*)d_in[4];  // (1024,512)
    const float* W_hh   = (const float*)d_in[5];  // (1024,256)
    const float* b_ih   = (const float*)d_in[6];  // (1024,)
    const float* b_hh   = (const float*)d_in[7];  // (1024,)
    float* out = (float*)d_out;                   // (T,B,256)

    (void)in_sizes; (void)n_in; (void)out_size;

    k_init<<<128, 256>>>(out);                    // h=c=0, out[0]=0

    dim3 gtr(BB, 32);
    k_tr<<<gtr, 256>>>(memory);                   // fp16 [b][s][e] copy

    dim3 gmp(4, 1024);
    k_memproj<<<gmp, 256>>>(memory, W_attn, b_attn);

    for (int t = 1; t < TT; t++) {
        k_attn<<<BB, 512>>>(W_attn);
        dim3 gg(32, 4, 3);
        k_gemm<<<gg, 256>>>(tgt + (size_t)t * BB * DD, W_ih, W_hh);
        k_cell<<<128, 256>>>(b_ih, b_hh, out + (size_t)t * BB * DD);
    }
}

// round 9
// speedup vs baseline: 1.6875x; 1.4690x over previous
#include <cuda_runtime.h>
#include <cuda_fp16.h>
#include <math.h>

// Problem constants
#define TT 256   // T (time steps)
#define BB 128   // batch
#define SS 512   // memory sequence length
#define DD 256   // EMBED = HID = ENC = DEC
#define GG 1024  // 4*HID gates

// ---------------- scratch (__device__ globals; no allocation allowed) ----------------
__device__ float g_memproj[BB * SS * DD];   // [b][s][d] fp32 : 67 MB
__device__ __half g_memt[BB * SS * DD];     // [b][s][e] fp16 : 34 MB
__device__ float g_h[2][BB * DD];           // double-buffered by step parity
__device__ float g_c[2][BB * DD];
__device__ float g_esum[BB * SS];           // energy logits
__device__ float g_ctxp[4][BB * DD];        // ctx partials per s-chunk
__device__ float g_gp[3][BB * GG];          // split-K gate partials

// ---------------- fast math (MUFU-based, ~1e-6 rel err) ----------------
__device__ __forceinline__ float fast_tanh(float x) {
    x = fminf(fmaxf(x, -15.f), 15.f);
    float e = __expf(2.f * x);
    return __fdividef(e - 1.f, e + 1.f);
}
__device__ __forceinline__ float fast_sigmoid(float x) {
    return __fdividef(1.f, 1.f + __expf(-x));
}

// ---------------- fused prologue: memproj GEMM + fp16 transpose + init ----------------
// grid (4, 1024), 256 thr. Linear block id L = by*4+bx in 0..4095.
//  - memproj tile (n0 = bx*64, m0 = by*64)
//  - transpose tile: b = L>>5, sc = L&31 -> s in [sc*16, sc*16+16)
//  - init: L < 128 zeroes g_h[0]/g_c[0]/out0 chunk
__global__ __launch_bounds__(256) void k_pre(const float* __restrict__ memory,
                                             const float* __restrict__ W_attn,
                                             const float* __restrict__ b_attn,
                                             float* __restrict__ out0) {
    __shared__ __align__(16) float Ash[32][68];
    __shared__ __align__(16) float Bsh[32][68];
    int tid = threadIdx.x;
    int tx = tid & 15, ty = tid >> 4;
    int n0 = blockIdx.x * 64;
    int m0 = blockIdx.y * 64;
    int L = blockIdx.y * 4 + blockIdx.x;

    // ---- init chunk ----
    if (L < 128) {
        int idx = L * 256 + tid;
        g_h[0][idx] = 0.f;
        g_c[0][idx] = 0.f;
        out0[idx] = 0.f;
    }

    // ---- fp16 transpose tile ----
    {
        int b = L >> 5;
        int sc = L & 31;
#pragma unroll
        for (int i = 0; i < 16; i++) {
            int s = sc * 16 + i;
            g_memt[(size_t)b * SS * DD + (size_t)s * DD + tid] =
                __float2half(memory[((size_t)s * BB + b) * DD + tid]);
        }
    }

    // ---- memproj GEMM tile ----
    float acc[4][4];
#pragma unroll
    for (int i = 0; i < 4; i++)
#pragma unroll
        for (int j = 0; j < 4; j++) acc[i][j] = 0.f;

    for (int k0 = 0; k0 < DD; k0 += 32) {
#pragma unroll
        for (int i = 0; i < 8; i++) {
            int idx = tid + i * 256;
            int e = idx & 31;
            int m = idx >> 5;
            int r = m0 + m;
            int b = r >> 9;
            int s = r & 511;
            Ash[e][m] = memory[((size_t)(s * BB + b)) * DD + k0 + e];
            int d = m;
            Bsh[e][d] = W_attn[(size_t)(n0 + d) * (2 * DD) + DD + k0 + e];
        }
        __syncthreads();
#pragma unroll
        for (int k = 0; k < 32; k++) {
            float4 a = *(const float4*)&Ash[k][ty * 4];
            float4 bv = *(const float4*)&Bsh[k][tx * 4];
            float av[4] = {a.x, a.y, a.z, a.w};
            float bw[4] = {bv.x, bv.y, bv.z, bv.w};
#pragma unroll
            for (int i = 0; i < 4; i++)
#pragma unroll
                for (int j = 0; j < 4; j++) acc[i][j] = fmaf(av[i], bw[j], acc[i][j]);
        }
        __syncthreads();
    }
    float4 bias = *(const float4*)&b_attn[n0 + tx * 4];
#pragma unroll
    for (int i = 0; i < 4; i++) {
        int r = m0 + ty * 4 + i;
        float4 o;
        o.x = acc[i][0] + bias.x;
        o.y = acc[i][1] + bias.y;
        o.z = acc[i][2] + bias.z;
        o.w = acc[i][3] + bias.w;
        *(float4*)&g_memproj[(size_t)r * DD + n0 + tx * 4] = o;
    }
}

// ---------------- per-step: fused LSTM-cell(t-1) + energy(t) ----------------
// grid (4 s-chunks, 128 b), 512 thr.
// Phase A (t>1): compute h_{t-1}, c_{t-1} from step t-1 gate partials (redundant
//   across the 4 chunk-blocks; identical values; c double-buffered so RMW is safe).
//   Writes out[t-1]. Keeps h in shared for phase B.
// Phase B: e_sum[b][s] = sum_d tanh(mem_proj[b,s,d] + hWh[b,d])
__global__ __launch_bounds__(512) void k_energy(const float* __restrict__ W_attn,
                                                const float* __restrict__ b_ih,
                                                const float* __restrict__ b_hh,
                                                float* __restrict__ out_prev,
                                                int t) {
    __shared__ __align__(16) float sh_h[DD];
    __shared__ __align__(16) float sh_w[DD];

    int c = blockIdx.x;          // s-chunk
    int b = blockIdx.y;
    int tid = threadIdx.x;
    int lane = tid & 31;
    int warp = tid >> 5;         // 16 warps

    if (tid < DD) {
        int hd = tid;
        if (t > 1) {
            int rp = t & 1;            // c_{t-2} parity
            int wp = (t + 1) & 1;      // c_{t-1} parity
            size_t base = (size_t)b * GG;
            float vi = g_gp[0][base + hd] + g_gp[1][base + hd] + g_gp[2][base + hd]
                     + b_ih[hd] + b_hh[hd];
            float vf = g_gp[0][base + hd + 256] + g_gp[1][base + hd + 256] + g_gp[2][base + hd + 256]
                     + b_ih[hd + 256] + b_hh[hd + 256];
            float vg = g_gp[0][base + hd + 512] + g_gp[1][base + hd + 512] + g_gp[2][base + hd + 512]
                     + b_ih[hd + 512] + b_hh[hd + 512];
            float vo = g_gp[0][base + hd + 768] + g_gp[1][base + hd + 768] + g_gp[2][base + hd + 768]
                     + b_ih[hd + 768] + b_hh[hd + 768];
            float gi = fast_sigmoid(vi);
            float gf = fast_sigmoid(vf);
            float gc = fast_tanh(vg);
            float go = fast_sigmoid(vo);
            float cc = gf * g_c[rp][b * DD + hd] + gi * gc;
            float hh = go * fast_tanh(cc);
            g_c[wp][b * DD + hd] = cc;
            g_h[wp][b * DD + hd] = hh;
            out_prev[b * DD + hd] = hh;
            sh_h[hd] = hh;
        } else {
            sh_h[hd] = 0.f;
        }
    }
    __syncthreads();

    // hWh[d] (redundant per chunk; cheap)
    for (int dd = 0; dd < 16; dd++) {
        int d = warp * 16 + dd;
        const float* wr = &W_attn[(size_t)d * (2 * DD)];
        float acc = 0.f;
#pragma unroll
        for (int j = 0; j < 8; j++) {
            int k = lane + j * 32;
            acc = fmaf(wr[k], sh_h[k], acc);
        }
#pragma unroll
        for (int o = 16; o; o >>= 1) acc += __shfl_xor_sync(0xffffffffu, acc, o);
        if (lane == 0) sh_w[d] = acc;
    }
    __syncthreads();

    const float4* wv = (const float4*)sh_w;
    float4 w0 = wv[lane];
    float4 w1 = wv[lane + 32];
    int sbase = c * 128;

    // 2 s per iteration: 4 independent float4 loads batched -> MLP 4
#pragma unroll
    for (int it = 0; it < 4; it++) {
        int s1 = sbase + warp + it * 32;
        int s2 = s1 + 16;
        const float4* mp1 = (const float4*)&g_memproj[((size_t)(b * SS + s1)) * DD];
        const float4* mp2 = (const float4*)&g_memproj[((size_t)(b * SS + s2)) * DD];
        float4 a0 = mp1[lane];
        float4 a1 = mp1[lane + 32];
        float4 b0 = mp2[lane];
        float4 b1 = mp2[lane + 32];
        float acc1 = fast_tanh(a0.x + w0.x) + fast_tanh(a0.y + w0.y) +
                     fast_tanh(a0.z + w0.z) + fast_tanh(a0.w + w0.w) +
                     fast_tanh(a1.x + w1.x) + fast_tanh(a1.y + w1.y) +
                     fast_tanh(a1.z + w1.z) + fast_tanh(a1.w + w1.w);
        float acc2 = fast_tanh(b0.x + w0.x) + fast_tanh(b0.y + w0.y) +
                     fast_tanh(b0.z + w0.z) + fast_tanh(b0.w + w0.w) +
                     fast_tanh(b1.x + w1.x) + fast_tanh(b1.y + w1.y) +
                     fast_tanh(b1.z + w1.z) + fast_tanh(b1.w + w1.w);
#pragma unroll
        for (int o = 16; o; o >>= 1) {
            acc1 += __shfl_xor_sync(0xffffffffu, acc1, o);
            acc2 += __shfl_xor_sync(0xffffffffu, acc2, o);
        }
        if (lane == 0) {
            g_esum[b * SS + s1] = acc1;
            g_esum[b * SS + s2] = acc2;
        }
    }
}

// ---------------- per-step softmax + ctx partial: grid (4 s-chunks, 128 b) ----------------
__global__ __launch_bounds__(512) void k_ctx() {
    __shared__ __align__(16) float sh_e[SS];
    __shared__ float sh_red[16];
    __shared__ float sh_sum[16];
    __shared__ __align__(16) float sh_ctxp[16][264];

    int c = blockIdx.x;
    int b = blockIdx.y;
    int tid = threadIdx.x;
    int lane = tid & 31;
    int warp = tid >> 5;

    float e = g_esum[b * SS + tid];   // one s per thread

    // softmax over all 512 s (redundant per chunk)
    float m = e;
#pragma unroll
    for (int o = 16; o; o >>= 1) m = fmaxf(m, __shfl_xor_sync(0xffffffffu, m, o));
    if (lane == 0) sh_red[warp] = m;
    __syncthreads();
    float mx = sh_red[0];
#pragma unroll
    for (int i = 1; i < 16; i++) mx = fmaxf(mx, sh_red[i]);
    float w = __expf(e - mx);
    float ws = w;
#pragma unroll
    for (int o = 16; o; o >>= 1) ws += __shfl_xor_sync(0xffffffffu, ws, o);
    if (lane == 0) sh_sum[warp] = ws;
    __syncthreads();
    float total = 0.f;
#pragma unroll
    for (int i = 0; i < 16; i++) total += sh_sum[i];
    float inv = __fdividef(1.f, total);
    sh_e[tid] = w * inv;
    __syncthreads();

    // partial ctx over this chunk's 128 s values
    {
        int e8 = tid & 31;   // e block of 8
        int sp = tid >> 5;   // 0..15
        const uint4* mb = (const uint4*)(g_memt + (size_t)b * SS * DD);
        float acc[8];
#pragma unroll
        for (int j = 0; j < 8; j++) acc[j] = 0.f;
#pragma unroll
        for (int k = 0; k < 8; k++) {
            int s = c * 128 + sp + k * 16;
            uint4 v = mb[s * 32 + e8];
            float a = sh_e[s];
            float2 f0 = __half22float2(*(__half2*)&v.x);
            float2 f1 = __half22float2(*(__half2*)&v.y);
            float2 f2 = __half22float2(*(__half2*)&v.z);
            float2 f3 = __half22float2(*(__half2*)&v.w);
            acc[0] = fmaf(a, f0.x, acc[0]);
            acc[1] = fmaf(a, f0.y, acc[1]);
            acc[2] = fmaf(a, f1.x, acc[2]);
            acc[3] = fmaf(a, f1.y, acc[3]);
            acc[4] = fmaf(a, f2.x, acc[4]);
            acc[5] = fmaf(a, f2.y, acc[5]);
            acc[6] = fmaf(a, f3.x, acc[6]);
            acc[7] = fmaf(a, f3.y, acc[7]);
        }
#pragma unroll
        for (int j = 0; j < 8; j++) sh_ctxp[sp][e8 * 8 + j] = acc[j];
    }
    __syncthreads();
    if (tid < DD) {
        float s = 0.f;
#pragma unroll
        for (int i = 0; i < 16; i++) s += sh_ctxp[i][tid];
        g_ctxp[c][b * DD + tid] = s;
    }
}

// ---------------- per-step gate GEMM, split-K x3 ----------------
// kz=0: tgt_t x W_ih[:, 0:256]; kz=1: ctx x W_ih[:, 256:512]; kz=2: h x W_hh
// hp = parity of the h buffer holding h_{t-1}
__global__ __launch_bounds__(256) void k_gemm(const float* __restrict__ tgt_t,
                                              const float* __restrict__ W_ih,
                                              const float* __restrict__ W_hh,
                                              int hp) {
    __shared__ __align__(16) float Ash[32][34];
    __shared__ __align__(16) float Bsh[32][34];
    int tid = threadIdx.x;
    int tx = tid & 15, ty = tid >> 4;
    int n0 = blockIdx.x * 32;
    int m0 = blockIdx.y * 32;
    int kz = blockIdx.z;

    const float* A;
    const float* W;
    int ldw, col0;
    if (kz == 0)      { A = tgt_t;    W = W_ih; ldw = 512; col0 = 0; }
    else if (kz == 1) { A = g_ctxp[0]; W = W_ih; ldw = 512; col0 = 256; }
    else              { A = g_h[hp];  W = W_hh; ldw = 256; col0 = 0; }

    float acc[2][2];
    acc[0][0] = acc[0][1] = acc[1][0] = acc[1][1] = 0.f;

    for (int k0 = 0; k0 < 256; k0 += 32) {
#pragma unroll
        for (int i = 0; i < 4; i++) {
            int idx = tid + i * 256;
            int k = idx & 31;
            int m = idx >> 5;
            int aidx = (m0 + m) * DD + k0 + k;
            float av;
            if (kz == 1) {
                av = g_ctxp[0][aidx] + g_ctxp[1][aidx] + g_ctxp[2][aidx] + g_ctxp[3][aidx];
            } else {
                av = A[aidx];
            }
            Ash[k][m] = av;
            int j = m;
            Bsh[k][j] = W[(size_t)(n0 + j) * ldw + col0 + k0 + k];
        }
        __syncthreads();
#pragma unroll
        for (int k = 0; k < 32; k++) {
            float2 a = *(const float2*)&Ash[k][ty * 2];
            float2 bv = *(const float2*)&Bsh[k][tx * 2];
            acc[0][0] = fmaf(a.x, bv.x, acc[0][0]);
            acc[0][1] = fmaf(a.x, bv.y, acc[0][1]);
            acc[1][0] = fmaf(a.y, bv.x, acc[1][0]);
            acc[1][1] = fmaf(a.y, bv.y, acc[1][1]);
        }
        __syncthreads();
    }
    int col = n0 + tx * 2;
#pragma unroll
    for (int i = 0; i < 2; i++) {
        int b = m0 + ty * 2 + i;
        float2 o = make_float2(acc[i][0], acc[i][1]);
        *(float2*)&g_gp[kz][(size_t)b * GG + col] = o;
    }
}

// ---------------- final LSTM cell: emits out[TT-1] ----------------
__global__ __launch_bounds__(256) void k_cell_final(const float* __restrict__ b_ih,
                                                    const float* __restrict__ b_hh,
                                                    float* __restrict__ out_t,
                                                    int rp) {
    int idx = blockIdx.x * blockDim.x + threadIdx.x;  // 0..32767
    int b = idx >> 8;
    int hd = idx & 255;
    size_t base = (size_t)b * GG;

    float vi = g_gp[0][base + hd] + g_gp[1][base + hd] + g_gp[2][base + hd]
             + b_ih[hd] + b_hh[hd];
    float vf = g_gp[0][base + hd + 256] + g_gp[1][base + hd + 256] + g_gp[2][base + hd + 256]
             + b_ih[hd + 256] + b_hh[hd + 256];
    float vg = g_gp[0][base + hd + 512] + g_gp[1][base + hd + 512] + g_gp[2][base + hd + 512]
             + b_ih[hd + 512] + b_hh[hd + 512];
    float vo = g_gp[0][base + hd + 768] + g_gp[1][base + hd + 768] + g_gp[2][base + hd + 768]
             + b_ih[hd + 768] + b_hh[hd + 768];

    float gi = fast_sigmoid(vi);
    float gf = fast_sigmoid(vf);
    float gc = fast_tanh(vg);
    float go = fast_sigmoid(vo);
    float c = gf * g_c[rp][idx] + gi * gc;
    float h = go * fast_tanh(c);
    out_t[idx] = h;
}

// ---------------- launch ----------------
// Graph node count: 1 (k_pre) + 255*3 (energy, ctx, gemm) + 1 (final cell) = 767
extern "C" void kernel_launch(void* const* d_in, const int* in_sizes, int n_in,
                              void* d_out, int out_size) {
    const float* tgt    = (const float*)d_in[0];  // (T,B,256)
    const float* memory = (const float*)d_in[1];  // (S,B,256)
    const float* W_attn = (const float*)d_in[2];  // (256,512)
    const float* b_attn = (const float*)d_in[3];  // (256,)
    const float* W_ih   = (const float*)d_in[4];  // (1024,512)
    const float* W_hh   = (const float*)d_in[5];  // (1024,256)
    const float* b_ih   = (const float*)d_in[6];  // (1024,)
    const float* b_hh   = (const float*)d_in[7];  // (1024,)
    float* out = (float*)d_out;                   // (T,B,256)

    (void)in_sizes; (void)n_in; (void)out_size;

    dim3 gmp(4, 1024);
    k_pre<<<gmp, 256>>>(memory, W_attn, b_attn, out);  // memproj + fp16 transpose + init

    for (int t = 1; t < TT; t++) {
        dim3 ge(4, BB);
        // fused cell(t-1) + energy(t); h_{t-1} lands in g_h[(t-1)&1] == g_h[(t+1)&1]
        k_energy<<<ge, 512>>>(W_attn, b_ih, b_hh, out + (size_t)(t - 1) * BB * DD, t);
        k_ctx<<<ge, 512>>>();
        dim3 gg(32, 4, 3);
        k_gemm<<<gg, 256>>>(tgt + (size_t)t * BB * DD, W_ih, W_hh, (t - 1) & 1);
    }
    // final cell for t = TT-1: reads c_{254} (parity 0), gates from gemm(255)
    k_cell_final<<<128, 256>>>(b_ih, b_hh, out + (size_t)(TT - 1) * BB * DD, (TT) & 1);
}

// round 10
// speedup vs baseline: 2.3793x; 1.4099x over previous
#include <cuda_runtime.h>
#include <cuda_fp16.h>
#include <math.h>

// Problem constants
#define TT 256   // T (time steps)
#define BB 128   // batch
#define SS 512   // memory sequence length
#define DD 256   // EMBED = HID = ENC = DEC
#define GG 1024  // 4*HID gates
#define NKZ 12   // gate-gemm split-K factor

// ---------------- scratch (__device__ globals; no allocation allowed) ----------------
__device__ __half g_memproj[BB * SS * DD];  // [b][s][d] fp16 : 34 MB
__device__ __half g_memt[BB * SS * DD];     // [b][s][e] fp16 : 34 MB
__device__ float g_h[2][BB * DD];           // double-buffered by step parity
__device__ float g_c[2][BB * DD];
__device__ float g_esum[BB * SS];           // energy logits
__device__ float g_ctxp[4][BB * DD];        // ctx partials per s-chunk
__device__ float g_gp[NKZ][BB * GG];        // split-K gate partials

// ---------------- fast math ----------------
__device__ __forceinline__ float tanh_approx(float x) {   // energy path only
    float y;
    asm("tanh.approx.f32 %0, %1;" : "=f"(y) : "f"(x));
    return y;
}
__device__ __forceinline__ float fast_tanh(float x) {     // accurate, cell path
    x = fminf(fmaxf(x, -15.f), 15.f);
    float e = __expf(2.f * x);
    return __fdividef(e - 1.f, e + 1.f);
}
__device__ __forceinline__ float fast_sigmoid(float x) {
    return __fdividef(1.f, 1.f + __expf(-x));
}

// ---------------- fused prologue: memproj GEMM (fp16 out) + fp16 transpose + init ----------------
// grid (4, 1024), 256 thr. Linear block id L = by*4+bx in 0..4095.
__global__ __launch_bounds__(256) void k_pre(const float* __restrict__ memory,
                                             const float* __restrict__ W_attn,
                                             const float* __restrict__ b_attn,
                                             float* __restrict__ out0) {
    __shared__ __align__(16) float Ash[32][68];
    __shared__ __align__(16) float Bsh[32][68];
    int tid = threadIdx.x;
    int tx = tid & 15, ty = tid >> 4;
    int n0 = blockIdx.x * 64;
    int m0 = blockIdx.y * 64;
    int L = blockIdx.y * 4 + blockIdx.x;

    // ---- init chunk ----
    if (L < 128) {
        int idx = L * 256 + tid;
        g_h[0][idx] = 0.f;
        g_c[0][idx] = 0.f;
        out0[idx] = 0.f;
    }

    // ---- fp16 transpose tile: memt[b][s][e] ----
    {
        int b = L >> 5;
        int sc = L & 31;
#pragma unroll
        for (int i = 0; i < 16; i++) {
            int s = sc * 16 + i;
            g_memt[(size_t)b * SS * DD + (size_t)s * DD + tid] =
                __float2half(memory[((size_t)s * BB + b) * DD + tid]);
        }
    }

    // ---- memproj GEMM tile ----
    float acc[4][4];
#pragma unroll
    for (int i = 0; i < 4; i++)
#pragma unroll
        for (int j = 0; j < 4; j++) acc[i][j] = 0.f;

    for (int k0 = 0; k0 < DD; k0 += 32) {
#pragma unroll
        for (int i = 0; i < 8; i++) {
            int idx = tid + i * 256;
            int e = idx & 31;
            int m = idx >> 5;
            int r = m0 + m;
            int b = r >> 9;
            int s = r & 511;
            Ash[e][m] = memory[((size_t)(s * BB + b)) * DD + k0 + e];
            int d = m;
            Bsh[e][d] = W_attn[(size_t)(n0 + d) * (2 * DD) + DD + k0 + e];
        }
        __syncthreads();
#pragma unroll
        for (int k = 0; k < 32; k++) {
            float4 a = *(const float4*)&Ash[k][ty * 4];
            float4 bv = *(const float4*)&Bsh[k][tx * 4];
            float av[4] = {a.x, a.y, a.z, a.w};
            float bw[4] = {bv.x, bv.y, bv.z, bv.w};
#pragma unroll
            for (int i = 0; i < 4; i++)
#pragma unroll
                for (int j = 0; j < 4; j++) acc[i][j] = fmaf(av[i], bw[j], acc[i][j]);
        }
        __syncthreads();
    }
    float4 bias = *(const float4*)&b_attn[n0 + tx * 4];
#pragma unroll
    for (int i = 0; i < 4; i++) {
        int r = m0 + ty * 4 + i;
        __half2 h0 = __floats2half2_rn(acc[i][0] + bias.x, acc[i][1] + bias.y);
        __half2 h1 = __floats2half2_rn(acc[i][2] + bias.z, acc[i][3] + bias.w);
        __half2* dst = (__half2*)&g_memproj[(size_t)r * DD + n0 + tx * 4];
        dst[0] = h0;
        dst[1] = h1;
    }
}

// ---------------- per-step: fused LSTM-cell(t-1) + energy(t) ----------------
// grid (4 s-chunks, 128 b), 512 thr.
__global__ __launch_bounds__(512) void k_energy(const float* __restrict__ W_attn,
                                                const float* __restrict__ b_ih,
                                                const float* __restrict__ b_hh,
                                                float* __restrict__ out_prev,
                                                int t) {
    __shared__ __align__(16) float sh_h[DD];
    __shared__ __align__(16) float sh_w[DD];

    int c = blockIdx.x;          // s-chunk
    int b = blockIdx.y;
    int tid = threadIdx.x;
    int lane = tid & 31;
    int warp = tid >> 5;         // 16 warps

    // Phase A: cell for step t-1 (redundant across 4 chunk-blocks; identical values)
    if (tid < DD) {
        int hd = tid;
        if (t > 1) {
            int rp = t & 1;            // c_{t-2} parity
            int wp = (t + 1) & 1;      // c_{t-1} parity
            size_t base = (size_t)b * GG;
            float vi = b_ih[hd] + b_hh[hd];
            float vf = b_ih[hd + 256] + b_hh[hd + 256];
            float vg = b_ih[hd + 512] + b_hh[hd + 512];
            float vo = b_ih[hd + 768] + b_hh[hd + 768];
#pragma unroll
            for (int p = 0; p < NKZ; p++) {
                vi += g_gp[p][base + hd];
                vf += g_gp[p][base + hd + 256];
                vg += g_gp[p][base + hd + 512];
                vo += g_gp[p][base + hd + 768];
            }
            float gi = fast_sigmoid(vi);
            float gf = fast_sigmoid(vf);
            float gc = fast_tanh(vg);
            float go = fast_sigmoid(vo);
            float cc = gf * g_c[rp][b * DD + hd] + gi * gc;
            float hh = go * fast_tanh(cc);
            g_c[wp][b * DD + hd] = cc;
            g_h[wp][b * DD + hd] = hh;
            out_prev[b * DD + hd] = hh;
            sh_h[hd] = hh;
        } else {
            sh_h[hd] = 0.f;
        }
    }
    __syncthreads();

    // hWh[d] (redundant per chunk; cheap)
    for (int dd = 0; dd < 16; dd++) {
        int d = warp * 16 + dd;
        const float* wr = &W_attn[(size_t)d * (2 * DD)];
        float acc = 0.f;
#pragma unroll
        for (int j = 0; j < 8; j++) {
            int k = lane + j * 32;
            acc = fmaf(wr[k], sh_h[k], acc);
        }
#pragma unroll
        for (int o = 16; o; o >>= 1) acc += __shfl_xor_sync(0xffffffffu, acc, o);
        if (lane == 0) sh_w[d] = acc;
    }
    __syncthreads();

    // Phase B: e_sum[b][s] = sum_d tanh(memproj[b,s,d] + hWh[d])
    // lane owns d = lane*8 .. lane*8+7; one uint4 (8 fp16) per s-row per lane
    float4 w0 = *(const float4*)&sh_w[lane * 8];
    float4 w1 = *(const float4*)&sh_w[lane * 8 + 4];
    int sbase = c * 128;
    const uint4* mpb = (const uint4*)g_memproj;   // 8 halves per uint4; 32 per row

#pragma unroll
    for (int it = 0; it < 4; it++) {
        int s1 = sbase + warp + it * 32;
        int s2 = s1 + 16;
        uint4 v1 = mpb[(size_t)(b * SS + s1) * 32 + lane];
        uint4 v2 = mpb[(size_t)(b * SS + s2) * 32 + lane];

        float2 p0 = __half22float2(*(__half2*)&v1.x);
        float2 p1 = __half22float2(*(((__half2*)&v1.x) + 1));
        float2 p2 = __half22float2(*(__half2*)&v1.z);
        float2 p3 = __half22float2(*(((__half2*)&v1.z) + 1));
        float acc1 = tanh_approx(p0.x + w0.x) + tanh_approx(p0.y + w0.y) +
                     tanh_approx(p1.x + w0.z) + tanh_approx(p1.y + w0.w) +
                     tanh_approx(p2.x + w1.x) + tanh_approx(p2.y + w1.y) +
                     tanh_approx(p3.x + w1.z) + tanh_approx(p3.y + w1.w);

        float2 q0 = __half22float2(*(__half2*)&v2.x);
        float2 q1 = __half22float2(*(((__half2*)&v2.x) + 1));
        float2 q2 = __half22float2(*(__half2*)&v2.z);
        float2 q3 = __half22float2(*(((__half2*)&v2.z) + 1));
        float acc2 = tanh_approx(q0.x + w0.x) + tanh_approx(q0.y + w0.y) +
                     tanh_approx(q1.x + w0.z) + tanh_approx(q1.y + w0.w) +
                     tanh_approx(q2.x + w1.x) + tanh_approx(q2.y + w1.y) +
                     tanh_approx(q3.x + w1.z) + tanh_approx(q3.y + w1.w);
#pragma unroll
        for (int o = 16; o; o >>= 1) {
            acc1 += __shfl_xor_sync(0xffffffffu, acc1, o);
            acc2 += __shfl_xor_sync(0xffffffffu, acc2, o);
        }
        if (lane == 0) {
            g_esum[b * SS + s1] = acc1;
            g_esum[b * SS + s2] = acc2;
        }
    }
}

// ---------------- per-step softmax + ctx partial: grid (4 s-chunks, 128 b) ----------------
__global__ __launch_bounds__(512) void k_ctx() {
    __shared__ __align__(16) float sh_e[SS];
    __shared__ float sh_red[16];
    __shared__ float sh_sum[16];
    __shared__ __align__(16) float sh_ctxp[16][264];

    int c = blockIdx.x;
    int b = blockIdx.y;
    int tid = threadIdx.x;
    int lane = tid & 31;
    int warp = tid >> 5;

    float e = g_esum[b * SS + tid];   // one s per thread

    // softmax over all 512 s (redundant per chunk)
    float m = e;
#pragma unroll
    for (int o = 16; o; o >>= 1) m = fmaxf(m, __shfl_xor_sync(0xffffffffu, m, o));
    if (lane == 0) sh_red[warp] = m;
    __syncthreads();
    float mx = sh_red[0];
#pragma unroll
    for (int i = 1; i < 16; i++) mx = fmaxf(mx, sh_red[i]);
    float w = __expf(e - mx);
    float ws = w;
#pragma unroll
    for (int o = 16; o; o >>= 1) ws += __shfl_xor_sync(0xffffffffu, ws, o);
    if (lane == 0) sh_sum[warp] = ws;
    __syncthreads();
    float total = 0.f;
#pragma unroll
    for (int i = 0; i < 16; i++) total += sh_sum[i];
    float inv = __fdividef(1.f, total);
    sh_e[tid] = w * inv;
    __syncthreads();

    // partial ctx over this chunk's 128 s values
    {
        int e8 = tid & 31;   // e block of 8
        int sp = tid >> 5;   // 0..15
        const uint4* mb = (const uint4*)(g_memt + (size_t)b * SS * DD);
        float acc[8];
#pragma unroll
        for (int j = 0; j < 8; j++) acc[j] = 0.f;
#pragma unroll
        for (int k = 0; k < 8; k++) {
            int s = c * 128 + sp + k * 16;
            uint4 v = mb[s * 32 + e8];
            float a = sh_e[s];
            float2 f0 = __half22float2(*(__half2*)&v.x);
            float2 f1 = __half22float2(*(((__half2*)&v.x) + 1));
            float2 f2 = __half22float2(*(__half2*)&v.z);
            float2 f3 = __half22float2(*(((__half2*)&v.z) + 1));
            acc[0] = fmaf(a, f0.x, acc[0]);
            acc[1] = fmaf(a, f0.y, acc[1]);
            acc[2] = fmaf(a, f1.x, acc[2]);
            acc[3] = fmaf(a, f1.y, acc[3]);
            acc[4] = fmaf(a, f2.x, acc[4]);
            acc[5] = fmaf(a, f2.y, acc[5]);
            acc[6] = fmaf(a, f3.x, acc[6]);
            acc[7] = fmaf(a, f3.y, acc[7]);
        }
#pragma unroll
        for (int j = 0; j < 8; j++) sh_ctxp[sp][e8 * 8 + j] = acc[j];
    }
    __syncthreads();
    if (tid < DD) {
        float s = 0.f;
#pragma unroll
        for (int i = 0; i < 16; i++) s += sh_ctxp[i][tid];
        g_ctxp[c][b * DD + tid] = s;
    }
}

// ---------------- per-step gate GEMM: BM=64 BN=64 BK=32, 4x4/thread, split-K x12 ----------------
// kz: src = kz>>2 (0:tgt,1:ctx,2:h), chunk = (kz&3)*64 within source's K=256.
// grid (16 n-tiles, 2 m-tiles, 12), 256 thr.
__global__ __launch_bounds__(256) void k_gemm(const float* __restrict__ tgt_t,
                                              const float* __restrict__ W_ih,
                                              const float* __restrict__ W_hh,
                                              int hp) {
    __shared__ __align__(16) float Ash[32][68];   // [k][m]
    __shared__ __align__(16) float Bsh[32][68];   // [k][j]
    int tid = threadIdx.x;
    int tx = tid & 15, ty = tid >> 4;
    int n0 = blockIdx.x * 64;
    int m0 = blockIdx.y * 64;
    int kz = blockIdx.z;
    int src = kz >> 2;
    int kc = (kz & 3) * 64;

    const float* A;
    const float* W;
    int ldw, col0;
    if (src == 0)      { A = tgt_t;   W = W_ih; ldw = 512; col0 = 0; }
    else if (src == 1) { A = g_ctxp[0]; W = W_ih; ldw = 512; col0 = 256; }
    else               { A = g_h[hp]; W = W_hh; ldw = 256; col0 = 0; }

    float acc[4][4];
#pragma unroll
    for (int i = 0; i < 4; i++)
#pragma unroll
        for (int j = 0; j < 4; j++) acc[i][j] = 0.f;

    for (int k0 = kc; k0 < kc + 64; k0 += 32) {
#pragma unroll
        for (int i = 0; i < 8; i++) {
            int idx = tid + i * 256;           // 0..2047
            int k = idx & 31;
            int m = idx >> 5;                  // 0..63
            int aidx = (m0 + m) * DD + k0 + k;
            float av;
            if (src == 1) {
                av = g_ctxp[0][aidx] + g_ctxp[1][aidx] + g_ctxp[2][aidx] + g_ctxp[3][aidx];
            } else {
                av = A[aidx];
            }
            Ash[k][m] = av;
            int j = m;
            Bsh[k][j] = W[(size_t)(n0 + j) * ldw + col0 + k0 + k];
        }
        __syncthreads();
#pragma unroll
        for (int k = 0; k < 32; k++) {
            float4 a = *(const float4*)&Ash[k][ty * 4];
            float4 bv = *(const float4*)&Bsh[k][tx * 4];
            float av[4] = {a.x, a.y, a.z, a.w};
            float bw[4] = {bv.x, bv.y, bv.z, bv.w};
#pragma unroll
            for (int i = 0; i < 4; i++)
#pragma unroll
                for (int j = 0; j < 4; j++) acc[i][j] = fmaf(av[i], bw[j], acc[i][j]);
        }
        __syncthreads();
    }
#pragma unroll
    for (int i = 0; i < 4; i++) {
        int b = m0 + ty * 4 + i;
        float4 o = make_float4(acc[i][0], acc[i][1], acc[i][2], acc[i][3]);
        *(float4*)&g_gp[kz][(size_t)b * GG + n0 + tx * 4] = o;
    }
}

// ---------------- final LSTM cell: emits out[TT-1] ----------------
__global__ __launch_bounds__(256) void k_cell_final(const float* __restrict__ b_ih,
                                                    const float* __restrict__ b_hh,
                                                    float* __restrict__ out_t,
                                                    int rp) {
    int idx = blockIdx.x * blockDim.x + threadIdx.x;  // 0..32767
    int b = idx >> 8;
    int hd = idx & 255;
    size_t base = (size_t)b * GG;

    float vi = b_ih[hd] + b_hh[hd];
    float vf = b_ih[hd + 256] + b_hh[hd + 256];
    float vg = b_ih[hd + 512] + b_hh[hd + 512];
    float vo = b_ih[hd + 768] + b_hh[hd + 768];
#pragma unroll
    for (int p = 0; p < NKZ; p++) {
        vi += g_gp[p][base + hd];
        vf += g_gp[p][base + hd + 256];
        vg += g_gp[p][base + hd + 512];
        vo += g_gp[p][base + hd + 768];
    }

    float gi = fast_sigmoid(vi);
    float gf = fast_sigmoid(vf);
    float gc = fast_tanh(vg);
    float go = fast_sigmoid(vo);
    float c = gf * g_c[rp][idx] + gi * gc;
    float h = go * fast_tanh(c);
    out_t[idx] = h;
}

// ---------------- launch ----------------
// Graph node count: 1 (k_pre) + 255*3 (energy, ctx, gemm) + 1 (final cell) = 767
extern "C" void kernel_launch(void* const* d_in, const int* in_sizes, int n_in,
                              void* d_out, int out_size) {
    const float* tgt    = (const float*)d_in[0];  // (T,B,256)
    const float* memory = (const float*)d_in[1];  // (S,B,256)
    const float* W_attn = (const float*)d_in[2];  // (256,512)
    const float* b_attn = (const float*)d_in[3];  // (256,)
    const float* W_ih   = (const float*)d_in[4];  // (1024,512)
    const float* W_hh   = (const float*)d_in[5];  // (1024,256)
    const float* b_ih   = (const float*)d_in[6];  // (1024,)
    const float* b_hh   = (const float*)d_in[7];  // (1024,)
    float* out = (float*)d_out;                   // (T,B,256)

    (void)in_sizes; (void)n_in; (void)out_size;

    dim3 gmp(4, 1024);
    k_pre<<<gmp, 256>>>(memory, W_attn, b_attn, out);  // memproj(fp16) + transpose + init

    for (int t = 1; t < TT; t++) {
        dim3 ge(4, BB);
        // fused cell(t-1) + energy(t); h_{t-1} lands in g_h[(t+1)&1]
        k_energy<<<ge, 512>>>(W_attn, b_ih, b_hh, out + (size_t)(t - 1) * BB * DD, t);
        k_ctx<<<ge, 512>>>();
        dim3 gg(16, 2, NKZ);
        k_gemm<<<gg, 256>>>(tgt + (size_t)t * BB * DD, W_ih, W_hh, (t - 1) & 1);
    }
    // final cell for t = TT-1: reads c_{254} (parity 0), gates from gemm(255)
    k_cell_final<<<128, 256>>>(b_ih, b_hh, out + (size_t)(TT - 1) * BB * DD, (TT) & 1);
}

// round 13
// speedup vs baseline: 2.8238x; 1.1868x over previous
#include <cuda_runtime.h>
#include <cuda_fp16.h>
#include <stdint.h>
#include <math.h>

// Problem constants
#define TT 256   // T (time steps)
#define BB 128   // batch
#define SS 512   // memory sequence length
#define DD 256   // EMBED = HID = ENC = DEC
#define GG 1024  // 4*HID gates
#define NKZ 3    // gate-gemm split-K (by source)

// ---------------- scratch (__device__ globals; no allocation allowed) ----------------
__device__ __half g_memproj[BB * SS * DD];  // [b][s][d] fp16 : 34 MB
__device__ __half g_memt[BB * SS * DD];     // [b][s][e] fp16 : 34 MB
__device__ __half g_w16[GG * 768];          // [j][k] fp16 gate weights (k: 0-511 W_ih, 512-767 W_hh)
__device__ float g_h[2][BB * DD];           // double-buffered by step parity
__device__ float g_c[2][BB * DD];
__device__ float g_esum[BB * SS];           // energy logits
__device__ float g_ctxp[4][BB * DD];        // ctx partials per s-chunk
__device__ float g_gp[NKZ][BB * GG];        // split-K gate partials

// ---------------- fast math ----------------
__device__ __forceinline__ float tanh_approx(float x) {   // energy path only
    float y;
    asm("tanh.approx.f32 %0, %1;" : "=f"(y) : "f"(x));
    return y;
}
__device__ __forceinline__ float fast_tanh(float x) {     // accurate, cell path
    x = fminf(fmaxf(x, -15.f), 15.f);
    float e = __expf(2.f * x);
    return __fdividef(e - 1.f, e + 1.f);
}
__device__ __forceinline__ float fast_sigmoid(float x) {
    return __fdividef(1.f, 1.f + __expf(-x));
}

// ---------------- fused prologue: memproj GEMM + transposes + weight conversion + init ----------------
// grid (4, 1024), 256 thr. Linear block id L = by*4+bx in 0..4095.
__global__ __launch_bounds__(256) void k_pre(const float* __restrict__ memory,
                                             const float* __restrict__ W_attn,
                                             const float* __restrict__ b_attn,
                                             const float* __restrict__ W_ih,
                                             const float* __restrict__ W_hh,
                                             float* __restrict__ out0) {
    __shared__ __align__(16) float Ash[32][68];
    __shared__ __align__(16) float Bsh[32][68];
    int tid = threadIdx.x;
    int tx = tid & 15, ty = tid >> 4;
    int n0 = blockIdx.x * 64;
    int m0 = blockIdx.y * 64;
    int L = blockIdx.y * 4 + blockIdx.x;

    // ---- init chunk ----
    if (L < 128) {
        int idx = L * 256 + tid;
        g_h[0][idx] = 0.f;
        g_c[0][idx] = 0.f;
        out0[idx] = 0.f;
    }

    // ---- fp16 gate-weight conversion: g_w16[j][0:512]=W_ih[j], [512:768]=W_hh[j] ----
    if (L < GG) {
        int j = L;
#pragma unroll
        for (int i = 0; i < 3; i++) {
            int k = tid + i * 256;
            float wv = (k < 512) ? W_ih[(size_t)j * 512 + k] : W_hh[(size_t)j * 256 + (k - 512)];
            g_w16[(size_t)j * 768 + k] = __float2half(wv);
        }
    }

    // ---- fp16 transpose tile: memt[b][s][e] ----
    {
        int b = L >> 5;
        int sc = L & 31;
#pragma unroll
        for (int i = 0; i < 16; i++) {
            int s = sc * 16 + i;
            g_memt[(size_t)b * SS * DD + (size_t)s * DD + tid] =
                __float2half(memory[((size_t)s * BB + b) * DD + tid]);
        }
    }

    // ---- memproj GEMM tile (fp16 out) ----
    float acc[4][4];
#pragma unroll
    for (int i = 0; i < 4; i++)
#pragma unroll
        for (int j = 0; j < 4; j++) acc[i][j] = 0.f;

    for (int k0 = 0; k0 < DD; k0 += 32) {
#pragma unroll
        for (int i = 0; i < 8; i++) {
            int idx = tid + i * 256;
            int e = idx & 31;
            int m = idx >> 5;
            int r = m0 + m;
            int b = r >> 9;
            int s = r & 511;
            Ash[e][m] = memory[((size_t)(s * BB + b)) * DD + k0 + e];
            int d = m;
            Bsh[e][d] = W_attn[(size_t)(n0 + d) * (2 * DD) + DD + k0 + e];
        }
        __syncthreads();
#pragma unroll
        for (int k = 0; k < 32; k++) {
            float4 a = *(const float4*)&Ash[k][ty * 4];
            float4 bv = *(const float4*)&Bsh[k][tx * 4];
            float av[4] = {a.x, a.y, a.z, a.w};
            float bw[4] = {bv.x, bv.y, bv.z, bv.w};
#pragma unroll
            for (int i = 0; i < 4; i++)
#pragma unroll
                for (int j = 0; j < 4; j++) acc[i][j] = fmaf(av[i], bw[j], acc[i][j]);
        }
        __syncthreads();
    }
    float4 bias = *(const float4*)&b_attn[n0 + tx * 4];
#pragma unroll
    for (int i = 0; i < 4; i++) {
        int r = m0 + ty * 4 + i;
        __half2 h0 = __floats2half2_rn(acc[i][0] + bias.x, acc[i][1] + bias.y);
        __half2 h1 = __floats2half2_rn(acc[i][2] + bias.z, acc[i][3] + bias.w);
        __half2* dst = (__half2*)&g_memproj[(size_t)r * DD + n0 + tx * 4];
        dst[0] = h0;
        dst[1] = h1;
    }
}

// ---------------- per-step: fused LSTM-cell(t-1) + energy(t) ----------------
// grid (4 s-chunks, 128 b), 512 thr.
__global__ __launch_bounds__(512) void k_energy(const float* __restrict__ W_attn,
                                                const float* __restrict__ b_ih,
                                                const float* __restrict__ b_hh,
                                                float* __restrict__ out_prev,
                                                int t) {
    __shared__ __align__(16) float sh_h[DD];
    __shared__ __align__(16) float sh_w[DD];

    int c = blockIdx.x;          // s-chunk
    int b = blockIdx.y;
    int tid = threadIdx.x;
    int lane = tid & 31;
    int warp = tid >> 5;         // 16 warps

    // Phase A: cell for step t-1 (redundant across 4 chunk-blocks; identical values)
    if (tid < DD) {
        int hd = tid;
        if (t > 1) {
            int rp = t & 1;            // c_{t-2} parity
            int wp = (t + 1) & 1;      // c_{t-1} parity
            size_t base = (size_t)b * GG;
            float vi = b_ih[hd] + b_hh[hd];
            float vf = b_ih[hd + 256] + b_hh[hd + 256];
            float vg = b_ih[hd + 512] + b_hh[hd + 512];
            float vo = b_ih[hd + 768] + b_hh[hd + 768];
#pragma unroll
            for (int p = 0; p < NKZ; p++) {
                vi += g_gp[p][base + hd];
                vf += g_gp[p][base + hd + 256];
                vg += g_gp[p][base + hd + 512];
                vo += g_gp[p][base + hd + 768];
            }
            float gi = fast_sigmoid(vi);
            float gf = fast_sigmoid(vf);
            float gc = fast_tanh(vg);
            float go = fast_sigmoid(vo);
            float cc = gf * g_c[rp][b * DD + hd] + gi * gc;
            float hh = go * fast_tanh(cc);
            g_c[wp][b * DD + hd] = cc;
            g_h[wp][b * DD + hd] = hh;
            out_prev[b * DD + hd] = hh;
            sh_h[hd] = hh;
        } else {
            sh_h[hd] = 0.f;
        }
    }
    __syncthreads();

    // hWh[d] (redundant per chunk; cheap)
    for (int dd = 0; dd < 16; dd++) {
        int d = warp * 16 + dd;
        const float* wr = &W_attn[(size_t)d * (2 * DD)];
        float acc = 0.f;
#pragma unroll
        for (int j = 0; j < 8; j++) {
            int k = lane + j * 32;
            acc = fmaf(wr[k], sh_h[k], acc);
        }
#pragma unroll
        for (int o = 16; o; o >>= 1) acc += __shfl_xor_sync(0xffffffffu, acc, o);
        if (lane == 0) sh_w[d] = acc;
    }
    __syncthreads();

    // Phase B: e_sum[b][s] = sum_d tanh(memproj[b,s,d] + hWh[d])
    float4 w0 = *(const float4*)&sh_w[lane * 8];
    float4 w1 = *(const float4*)&sh_w[lane * 8 + 4];
    int sbase = c * 128;
    const uint4* mpb = (const uint4*)g_memproj;   // 8 halves per uint4; 32 per row

#pragma unroll
    for (int it = 0; it < 4; it++) {
        int s1 = sbase + warp + it * 32;
        int s2 = s1 + 16;
        uint4 v1 = mpb[(size_t)(b * SS + s1) * 32 + lane];
        uint4 v2 = mpb[(size_t)(b * SS + s2) * 32 + lane];

        float2 p0 = __half22float2(*(__half2*)&v1.x);
        float2 p1 = __half22float2(*(((__half2*)&v1.x) + 1));
        float2 p2 = __half22float2(*(__half2*)&v1.z);
        float2 p3 = __half22float2(*(((__half2*)&v1.z) + 1));
        float acc1 = tanh_approx(p0.x + w0.x) + tanh_approx(p0.y + w0.y) +
                     tanh_approx(p1.x + w0.z) + tanh_approx(p1.y + w0.w) +
                     tanh_approx(p2.x + w1.x) + tanh_approx(p2.y + w1.y) +
                     tanh_approx(p3.x + w1.z) + tanh_approx(p3.y + w1.w);

        float2 q0 = __half22float2(*(__half2*)&v2.x);
        float2 q1 = __half22float2(*(((__half2*)&v2.x) + 1));
        float2 q2 = __half22float2(*(__half2*)&v2.z);
        float2 q3 = __half22float2(*(((__half2*)&v2.z) + 1));
        float acc2 = tanh_approx(q0.x + w0.x) + tanh_approx(q0.y + w0.y) +
                     tanh_approx(q1.x + w0.z) + tanh_approx(q1.y + w0.w) +
                     tanh_approx(q2.x + w1.x) + tanh_approx(q2.y + w1.y) +
                     tanh_approx(q3.x + w1.z) + tanh_approx(q3.y + w1.w);
#pragma unroll
        for (int o = 16; o; o >>= 1) {
            acc1 += __shfl_xor_sync(0xffffffffu, acc1, o);
            acc2 += __shfl_xor_sync(0xffffffffu, acc2, o);
        }
        if (lane == 0) {
            g_esum[b * SS + s1] = acc1;
            g_esum[b * SS + s2] = acc2;
        }
    }
}

// ---------------- per-step softmax + ctx partial: grid (4 s-chunks, 128 b) ----------------
__global__ __launch_bounds__(512) void k_ctx() {
    __shared__ __align__(16) float sh_e[SS];
    __shared__ float sh_red[16];
    __shared__ float sh_sum[16];
    __shared__ __align__(16) float sh_ctxp[16][264];

    int c = blockIdx.x;
    int b = blockIdx.y;
    int tid = threadIdx.x;
    int lane = tid & 31;
    int warp = tid >> 5;

    float e = g_esum[b * SS + tid];   // one s per thread

    float m = e;
#pragma unroll
    for (int o = 16; o; o >>= 1) m = fmaxf(m, __shfl_xor_sync(0xffffffffu, m, o));
    if (lane == 0) sh_red[warp] = m;
    __syncthreads();
    float mx = sh_red[0];
#pragma unroll
    for (int i = 1; i < 16; i++) mx = fmaxf(mx, sh_red[i]);
    float w = __expf(e - mx);
    float ws = w;
#pragma unroll
    for (int o = 16; o; o >>= 1) ws += __shfl_xor_sync(0xffffffffu, ws, o);
    if (lane == 0) sh_sum[warp] = ws;
    __syncthreads();
    float total = 0.f;
#pragma unroll
    for (int i = 0; i < 16; i++) total += sh_sum[i];
    float inv = __fdividef(1.f, total);
    sh_e[tid] = w * inv;
    __syncthreads();

    // partial ctx over this chunk's 128 s values
    {
        int e8 = tid & 31;   // e block of 8
        int sp = tid >> 5;   // 0..15
        const uint4* mb = (const uint4*)(g_memt + (size_t)b * SS * DD);
        float acc[8];
#pragma unroll
        for (int j = 0; j < 8; j++) acc[j] = 0.f;
#pragma unroll
        for (int k = 0; k < 8; k++) {
            int s = c * 128 + sp + k * 16;
            uint4 v = mb[s * 32 + e8];
            float a = sh_e[s];
            float2 f0 = __half22float2(*(__half2*)&v.x);
            float2 f1 = __half22float2(*(((__half2*)&v.x) + 1));
            float2 f2 = __half22float2(*(__half2*)&v.z);
            float2 f3 = __half22float2(*(((__half2*)&v.z) + 1));
            acc[0] = fmaf(a, f0.x, acc[0]);
            acc[1] = fmaf(a, f0.y, acc[1]);
            acc[2] = fmaf(a, f1.x, acc[2]);
            acc[3] = fmaf(a, f1.y, acc[3]);
            acc[4] = fmaf(a, f2.x, acc[4]);
            acc[5] = fmaf(a, f2.y, acc[5]);
            acc[6] = fmaf(a, f3.x, acc[6]);
            acc[7] = fmaf(a, f3.y, acc[7]);
        }
#pragma unroll
        for (int j = 0; j < 8; j++) sh_ctxp[sp][e8 * 8 + j] = acc[j];
    }
    __syncthreads();
    if (tid < DD) {
        float s = 0.f;
#pragma unroll
        for (int i = 0; i < 16; i++) s += sh_ctxp[i][tid];
        g_ctxp[c][b * DD + tid] = s;
    }
}

// ---------------- per-step gate GEMM via HMMA (mma.sync m16n8k16 fp16->fp32) ----------------
// gates_partial[kz][b][j] = sum_{k<256} A_src[b][k] * g_w16[j][kz*256 + k]
// Block: 128 thr (4 warps), BM=32, BN=32, full K=256 staged once.
// Warp w: m-offset (w>>1)*16, n-offset (w&1)*16 (two n8 mma tiles per k-step).
// grid (32 n-tiles, 4 m-tiles, 3 kz).
__global__ __launch_bounds__(128) void k_gemm(const float* __restrict__ tgt_t,
                                              int hp) {
    __shared__ __align__(16) __half sA[32][264];   // [m][k], pad 8 -> conflict-free frags
    __shared__ __align__(16) __half sB[32][264];   // [n][k]

    int tid = threadIdx.x;
    int lane = tid & 31;
    int warp = tid >> 5;       // 0..3
    int n0 = blockIdx.x * 32;
    int m0 = blockIdx.y * 32;
    int kz = blockIdx.z;       // source: 0 tgt, 1 ctx, 2 h

    // ---- stage A: 32 rows x 256 k, fp32 -> fp16 ----
    {
        const float* A = (kz == 0) ? tgt_t : (kz == 2 ? g_h[hp] : (const float*)0);
#pragma unroll
        for (int i = 0; i < 64; i++) {
            int idx = tid + i * 128;        // 0..8191
            int row = idx >> 8;
            int col = idx & 255;
            int aidx = (m0 + row) * DD + col;
            float av;
            if (kz == 1) {
                av = g_ctxp[0][aidx] + g_ctxp[1][aidx] + g_ctxp[2][aidx] + g_ctxp[3][aidx];
            } else {
                av = A[aidx];
            }
            sA[row][col] = __float2half(av);
        }
    }
    // ---- stage B: 32 n-rows x 256 k from g_w16 (fp16, uint4 = 8 halves) ----
    {
        const uint4* wb = (const uint4*)(g_w16 + (size_t)kz * 256);
        // row j: g_w16[(n0+j)*768 + kz*256 + c4*8]; 768 halves = 96 uint4 per row
#pragma unroll
        for (int i = 0; i < 8; i++) {
            int idx = tid + i * 128;        // 0..1023
            int row = idx >> 5;
            int c4 = idx & 31;
            uint4 v = wb[(size_t)(n0 + row) * 96 + c4];
            *(uint4*)&sB[row][c4 * 8] = v;
        }
    }
    __syncthreads();

    // ---- mma mainloop: 16 k-steps of k16 ----
    int g = lane >> 2;          // groupID 0..7
    int tg = lane & 3;          // threadID_in_group
    int mw = (warp >> 1) * 16;
    int nw = (warp & 1) * 16;

    float d0[4] = {0.f, 0.f, 0.f, 0.f};   // n-tile 0 (cols nw+0..7)
    float d1[4] = {0.f, 0.f, 0.f, 0.f};   // n-tile 1 (cols nw+8..15)

#pragma unroll
    for (int ks = 0; ks < 16; ks++) {
        int k0 = ks * 16;
        int kc = k0 + tg * 2;
        uint32_t a0 = *(const uint32_t*)&sA[mw + g][kc];
        uint32_t a1 = *(const uint32_t*)&sA[mw + g + 8][kc];
        uint32_t a2 = *(const uint32_t*)&sA[mw + g][kc + 8];
        uint32_t a3 = *(const uint32_t*)&sA[mw + g + 8][kc + 8];

        uint32_t b0 = *(const uint32_t*)&sB[nw + g][kc];
        uint32_t b1 = *(const uint32_t*)&sB[nw + g][kc + 8];
        uint32_t b2 = *(const uint32_t*)&sB[nw + 8 + g][kc];
        uint32_t b3 = *(const uint32_t*)&sB[nw + 8 + g][kc + 8];

        asm volatile(
            "mma.sync.aligned.m16n8k16.row.col.f32.f16.f16.f32 "
            "{%0,%1,%2,%3}, {%4,%5,%6,%7}, {%8,%9}, {%0,%1,%2,%3};\n"
            : "+f"(d0[0]), "+f"(d0[1]), "+f"(d0[2]), "+f"(d0[3])
            : "r"(a0), "r"(a1), "r"(a2), "r"(a3), "r"(b0), "r"(b1));
        asm volatile(
            "mma.sync.aligned.m16n8k16.row.col.f32.f16.f16.f32 "
            "{%0,%1,%2,%3}, {%4,%5,%6,%7}, {%8,%9}, {%0,%1,%2,%3};\n"
            : "+f"(d1[0]), "+f"(d1[1]), "+f"(d1[2]), "+f"(d1[3])
            : "r"(a0), "r"(a1), "r"(a2), "r"(a3), "r"(b2), "r"(b3));
    }

    // ---- epilogue: d layout row=g(+8), cols=2*tg(+1); write float2 ----
    {
        int r0 = m0 + mw + g;
        int r1 = r0 + 8;
        int c0 = n0 + nw + tg * 2;
        float* gp = g_gp[kz];
        *(float2*)&gp[(size_t)r0 * GG + c0]      = make_float2(d0[0], d0[1]);
        *(float2*)&gp[(size_t)r1 * GG + c0]      = make_float2(d0[2], d0[3]);
        *(float2*)&gp[(size_t)r0 * GG + c0 + 8]  = make_float2(d1[0], d1[1]);
        *(float2*)&gp[(size_t)r1 * GG + c0 + 8]  = make_float2(d1[2], d1[3]);
    }
}

// ---------------- final LSTM cell: emits out[TT-1] ----------------
__global__ __launch_bounds__(256) void k_cell_final(const float* __restrict__ b_ih,
                                                    const float* __restrict__ b_hh,
                                                    float* __restrict__ out_t,
                                                    int rp) {
    int idx = blockIdx.x * blockDim.x + threadIdx.x;  // 0..32767
    int b = idx >> 8;
    int hd = idx & 255;
    size_t base = (size_t)b * GG;

    float vi = b_ih[hd] + b_hh[hd];
    float vf = b_ih[hd + 256] + b_hh[hd + 256];
    float vg = b_ih[hd + 512] + b_hh[hd + 512];
    float vo = b_ih[hd + 768] + b_hh[hd + 768];
#pragma unroll
    for (int p = 0; p < NKZ; p++) {
        vi += g_gp[p][base + hd];
        vf += g_gp[p][base + hd + 256];
        vg += g_gp[p][base + hd + 512];
        vo += g_gp[p][base + hd + 768];
    }

    float gi = fast_sigmoid(vi);
    float gf = fast_sigmoid(vf);
    float gc = fast_tanh(vg);
    float go = fast_sigmoid(vo);
    float c = gf * g_c[rp][idx] + gi * gc;
    float h = go * fast_tanh(c);
    out_t[idx] = h;
}

// ---------------- launch ----------------
// Graph node count: 1 (k_pre) + 255*3 (energy, ctx, gemm) + 1 (final cell) = 767
extern "C" void kernel_launch(void* const* d_in, const int* in_sizes, int n_in,
                              void* d_out, int out_size) {
    const float* tgt    = (const float*)d_in[0];  // (T,B,256)
    const float* memory = (const float*)d_in[1];  // (S,B,256)
    const float* W_attn = (const float*)d_in[2];  // (256,512)
    const float* b_attn = (const float*)d_in[3];  // (256,)
    const float* W_ih   = (const float*)d_in[4];  // (1024,512)
    const float* W_hh   = (const float*)d_in[5];  // (1024,256)
    const float* b_ih   = (const float*)d_in[6];  // (1024,)
    const float* b_hh   = (const float*)d_in[7];  // (1024,)
    float* out = (float*)d_out;                   // (T,B,256)

    (void)in_sizes; (void)n_in; (void)out_size;

    dim3 gmp(4, 1024);
    k_pre<<<gmp, 256>>>(memory, W_attn, b_attn, W_ih, W_hh, out);

    for (int t = 1; t < TT; t++) {
        dim3 ge(4, BB);
        // fused cell(t-1) + energy(t); h_{t-1} lands in g_h[(t+1)&1]
        k_energy<<<ge, 512>>>(W_attn, b_ih, b_hh, out + (size_t)(t - 1) * BB * DD, t);
        k_ctx<<<ge, 512>>>();
        dim3 gg(32, 4, NKZ);
        k_gemm<<<gg, 128>>>(tgt + (size_t)t * BB * DD, (t - 1) & 1);
    }
    // final cell for t = TT-1: reads c_{254} (parity 0), gates from gemm(255)
    k_cell_final<<<128, 256>>>(b_ih, b_hh, out + (size_t)(TT - 1) * BB * DD, (TT) & 1);
}

// round 14
// speedup vs baseline: 2.9333x; 1.0388x over previous
#include <cuda_runtime.h>
#include <cuda_fp16.h>
#include <stdint.h>
#include <math.h>

// Problem constants
#define TT 256   // T (time steps)
#define BB 128   // batch
#define SS 512   // memory sequence length
#define DD 256   // EMBED = HID = ENC = DEC
#define GG 1024  // 4*HID gates
#define NKZ 2    // per-step gate-gemm split (ctx, h)

// ---------------- scratch (__device__ globals; no allocation allowed) ----------------
__device__ __half g_memproj[BB * SS * DD];  // [b][s][d] fp16 : 34 MB
__device__ __half g_memt[BB * SS * DD];     // [b][s][e] fp16 : 34 MB
__device__ __half g_w16[GG * 768];          // [j][k] fp16 gate weights (0-511 W_ih, 512-767 W_hh)
__device__ float g_gpre[TT * BB * GG];      // precomputed tgt gate partial : 134 MB
__device__ float g_h[2][BB * DD];           // double-buffered by step parity
__device__ float g_c[2][BB * DD];
__device__ float g_esum[BB * SS];           // energy logits
__device__ float g_ctxp[4][BB * DD];        // ctx partials per s-chunk
__device__ float g_gp[NKZ][BB * GG];        // per-step gate partials (ctx, h)

// ---------------- fast math ----------------
__device__ __forceinline__ float tanh_approx(float x) {   // energy path only
    float y;
    asm("tanh.approx.f32 %0, %1;" : "=f"(y) : "f"(x));
    return y;
}
__device__ __forceinline__ float fast_tanh(float x) {     // accurate, cell path
    x = fminf(fmaxf(x, -15.f), 15.f);
    float e = __expf(2.f * x);
    return __fdividef(e - 1.f, e + 1.f);
}
__device__ __forceinline__ float fast_sigmoid(float x) {
    return __fdividef(1.f, 1.f + __expf(-x));
}

// ---------------- fused prologue: memproj GEMM + transposes + weight conversion + init ----------------
// grid (4, 1024), 256 thr. Linear block id L = by*4+bx in 0..4095.
__global__ __launch_bounds__(256) void k_pre(const float* __restrict__ memory,
                                             const float* __restrict__ W_attn,
                                             const float* __restrict__ b_attn,
                                             const float* __restrict__ W_ih,
                                             const float* __restrict__ W_hh,
                                             float* __restrict__ out0) {
    __shared__ __align__(16) float Ash[32][68];
    __shared__ __align__(16) float Bsh[32][68];
    int tid = threadIdx.x;
    int tx = tid & 15, ty = tid >> 4;
    int n0 = blockIdx.x * 64;
    int m0 = blockIdx.y * 64;
    int L = blockIdx.y * 4 + blockIdx.x;

    // ---- init chunk ----
    if (L < 128) {
        int idx = L * 256 + tid;
        g_h[0][idx] = 0.f;
        g_c[0][idx] = 0.f;
        out0[idx] = 0.f;
    }

    // ---- fp16 gate-weight conversion ----
    if (L < GG) {
        int j = L;
#pragma unroll
        for (int i = 0; i < 3; i++) {
            int k = tid + i * 256;
            float wv = (k < 512) ? W_ih[(size_t)j * 512 + k] : W_hh[(size_t)j * 256 + (k - 512)];
            g_w16[(size_t)j * 768 + k] = __float2half(wv);
        }
    }

    // ---- fp16 transpose tile: memt[b][s][e] ----
    {
        int b = L >> 5;
        int sc = L & 31;
#pragma unroll
        for (int i = 0; i < 16; i++) {
            int s = sc * 16 + i;
            g_memt[(size_t)b * SS * DD + (size_t)s * DD + tid] =
                __float2half(memory[((size_t)s * BB + b) * DD + tid]);
        }
    }

    // ---- memproj GEMM tile (fp16 out) ----
    float acc[4][4];
#pragma unroll
    for (int i = 0; i < 4; i++)
#pragma unroll
        for (int j = 0; j < 4; j++) acc[i][j] = 0.f;

    for (int k0 = 0; k0 < DD; k0 += 32) {
#pragma unroll
        for (int i = 0; i < 8; i++) {
            int idx = tid + i * 256;
            int e = idx & 31;
            int m = idx >> 5;
            int r = m0 + m;
            int b = r >> 9;
            int s = r & 511;
            Ash[e][m] = memory[((size_t)(s * BB + b)) * DD + k0 + e];
            int d = m;
            Bsh[e][d] = W_attn[(size_t)(n0 + d) * (2 * DD) + DD + k0 + e];
        }
        __syncthreads();
#pragma unroll
        for (int k = 0; k < 32; k++) {
            float4 a = *(const float4*)&Ash[k][ty * 4];
            float4 bv = *(const float4*)&Bsh[k][tx * 4];
            float av[4] = {a.x, a.y, a.z, a.w};
            float bw[4] = {bv.x, bv.y, bv.z, bv.w};
#pragma unroll
            for (int i = 0; i < 4; i++)
#pragma unroll
                for (int j = 0; j < 4; j++) acc[i][j] = fmaf(av[i], bw[j], acc[i][j]);
        }
        __syncthreads();
    }
    float4 bias = *(const float4*)&b_attn[n0 + tx * 4];
#pragma unroll
    for (int i = 0; i < 4; i++) {
        int r = m0 + ty * 4 + i;
        __half2 h0 = __floats2half2_rn(acc[i][0] + bias.x, acc[i][1] + bias.y);
        __half2 h1 = __floats2half2_rn(acc[i][2] + bias.z, acc[i][3] + bias.w);
        __half2* dst = (__half2*)&g_memproj[(size_t)r * DD + n0 + tx * 4];
        dst[0] = h0;
        dst[1] = h1;
    }
}

// ---------------- prologue HMMA: g_gpre[r][j] = sum_k tgt_flat[r][k] * W_ih[j][k], k<256 ----------------
// r = t*128+b (tgt is (T,B,256) row-major => flat [32768][256]).
// BM=32, BN=32, 128 thr / 4 warps, full K=256 staged. grid (32 n-tiles, 1024 m-tiles).
__global__ __launch_bounds__(128) void k_pregemm(const float* __restrict__ tgt) {
    __shared__ __align__(16) __half sA[32][264];
    __shared__ __align__(16) __half sB[32][264];

    int tid = threadIdx.x;
    int lane = tid & 31;
    int warp = tid >> 5;
    int n0 = blockIdx.x * 32;
    int m0 = blockIdx.y * 32;

    // stage A: 32 rows x 256 (float4 vectorized: 2048 float4s)
#pragma unroll
    for (int i = 0; i < 16; i++) {
        int idx = tid + i * 128;          // 0..2047
        int row = idx >> 6;               // 64 float4 per row
        int c4 = idx & 63;
        float4 v = *(const float4*)&tgt[(size_t)(m0 + row) * DD + c4 * 4];
        *(__half2*)&sA[row][c4 * 4]     = __floats2half2_rn(v.x, v.y);
        *(__half2*)&sA[row][c4 * 4 + 2] = __floats2half2_rn(v.z, v.w);
    }
    // stage B: rows n0..n0+31, cols 0..255 of g_w16 (96 uint4 per row)
    {
        const uint4* wb = (const uint4*)g_w16;
#pragma unroll
        for (int i = 0; i < 8; i++) {
            int idx = tid + i * 128;
            int row = idx >> 5;
            int c4 = idx & 31;
            uint4 v = wb[(size_t)(n0 + row) * 96 + c4];
            *(uint4*)&sB[row][c4 * 8] = v;
        }
    }
    __syncthreads();

    int g = lane >> 2;
    int tg = lane & 3;
    int mw = (warp >> 1) * 16;
    int nw = (warp & 1) * 16;

    float d0[4] = {0.f, 0.f, 0.f, 0.f};
    float d1[4] = {0.f, 0.f, 0.f, 0.f};

#pragma unroll
    for (int ks = 0; ks < 16; ks++) {
        int kc = ks * 16 + tg * 2;
        uint32_t a0 = *(const uint32_t*)&sA[mw + g][kc];
        uint32_t a1 = *(const uint32_t*)&sA[mw + g + 8][kc];
        uint32_t a2 = *(const uint32_t*)&sA[mw + g][kc + 8];
        uint32_t a3 = *(const uint32_t*)&sA[mw + g + 8][kc + 8];
        uint32_t b0 = *(const uint32_t*)&sB[nw + g][kc];
        uint32_t b1 = *(const uint32_t*)&sB[nw + g][kc + 8];
        uint32_t b2 = *(const uint32_t*)&sB[nw + 8 + g][kc];
        uint32_t b3 = *(const uint32_t*)&sB[nw + 8 + g][kc + 8];

        asm volatile(
            "mma.sync.aligned.m16n8k16.row.col.f32.f16.f16.f32 "
            "{%0,%1,%2,%3}, {%4,%5,%6,%7}, {%8,%9}, {%0,%1,%2,%3};\n"
            : "+f"(d0[0]), "+f"(d0[1]), "+f"(d0[2]), "+f"(d0[3])
            : "r"(a0), "r"(a1), "r"(a2), "r"(a3), "r"(b0), "r"(b1));
        asm volatile(
            "mma.sync.aligned.m16n8k16.row.col.f32.f16.f16.f32 "
            "{%0,%1,%2,%3}, {%4,%5,%6,%7}, {%8,%9}, {%0,%1,%2,%3};\n"
            : "+f"(d1[0]), "+f"(d1[1]), "+f"(d1[2]), "+f"(d1[3])
            : "r"(a0), "r"(a1), "r"(a2), "r"(a3), "r"(b2), "r"(b3));
    }

    {
        int r0 = m0 + mw + g;
        int r1 = r0 + 8;
        int c0 = n0 + nw + tg * 2;
        *(float2*)&g_gpre[(size_t)r0 * GG + c0]     = make_float2(d0[0], d0[1]);
        *(float2*)&g_gpre[(size_t)r1 * GG + c0]     = make_float2(d0[2], d0[3]);
        *(float2*)&g_gpre[(size_t)r0 * GG + c0 + 8] = make_float2(d1[0], d1[1]);
        *(float2*)&g_gpre[(size_t)r1 * GG + c0 + 8] = make_float2(d1[2], d1[3]);
    }
}

// ---------------- per-step: fused LSTM-cell(t-1) + energy(t) ----------------
// grid (4 s-chunks, 128 b), 512 thr.
__global__ __launch_bounds__(512) void k_energy(const float* __restrict__ W_attn,
                                                const float* __restrict__ b_ih,
                                                const float* __restrict__ b_hh,
                                                float* __restrict__ out_prev,
                                                int t) {
    __shared__ __align__(16) float sh_h[DD];
    __shared__ __align__(16) float sh_w[DD];

    int c = blockIdx.x;
    int b = blockIdx.y;
    int tid = threadIdx.x;
    int lane = tid & 31;
    int warp = tid >> 5;

    // Phase A: cell for step t-1 (redundant across the 4 chunk-blocks)
    if (tid < DD) {
        int hd = tid;
        if (t > 1) {
            int rp = t & 1;            // c_{t-2} parity
            int wp = (t + 1) & 1;      // c_{t-1} parity
            size_t base = (size_t)b * GG;
            size_t pre = ((size_t)(t - 1) * BB + b) * GG;
            float vi = b_ih[hd] + b_hh[hd] + g_gpre[pre + hd];
            float vf = b_ih[hd + 256] + b_hh[hd + 256] + g_gpre[pre + hd + 256];
            float vg = b_ih[hd + 512] + b_hh[hd + 512] + g_gpre[pre + hd + 512];
            float vo = b_ih[hd + 768] + b_hh[hd + 768] + g_gpre[pre + hd + 768];
#pragma unroll
            for (int p = 0; p < NKZ; p++) {
                vi += g_gp[p][base + hd];
                vf += g_gp[p][base + hd + 256];
                vg += g_gp[p][base + hd + 512];
                vo += g_gp[p][base + hd + 768];
            }
            float gi = fast_sigmoid(vi);
            float gf = fast_sigmoid(vf);
            float gc = fast_tanh(vg);
            float go = fast_sigmoid(vo);
            float cc = gf * g_c[rp][b * DD + hd] + gi * gc;
            float hh = go * fast_tanh(cc);
            g_c[wp][b * DD + hd] = cc;
            g_h[wp][b * DD + hd] = hh;
            out_prev[b * DD + hd] = hh;
            sh_h[hd] = hh;
        } else {
            sh_h[hd] = 0.f;
        }
    }
    __syncthreads();

    // hWh[d]
    for (int dd = 0; dd < 16; dd++) {
        int d = warp * 16 + dd;
        const float* wr = &W_attn[(size_t)d * (2 * DD)];
        float acc = 0.f;
#pragma unroll
        for (int j = 0; j < 8; j++) {
            int k = lane + j * 32;
            acc = fmaf(wr[k], sh_h[k], acc);
        }
#pragma unroll
        for (int o = 16; o; o >>= 1) acc += __shfl_xor_sync(0xffffffffu, acc, o);
        if (lane == 0) sh_w[d] = acc;
    }
    __syncthreads();

    // Phase B: e_sum
    float4 w0 = *(const float4*)&sh_w[lane * 8];
    float4 w1 = *(const float4*)&sh_w[lane * 8 + 4];
    int sbase = c * 128;
    const uint4* mpb = (const uint4*)g_memproj;

#pragma unroll
    for (int it = 0; it < 4; it++) {
        int s1 = sbase + warp + it * 32;
        int s2 = s1 + 16;
        uint4 v1 = mpb[(size_t)(b * SS + s1) * 32 + lane];
        uint4 v2 = mpb[(size_t)(b * SS + s2) * 32 + lane];

        float2 p0 = __half22float2(*(__half2*)&v1.x);
        float2 p1 = __half22float2(*(((__half2*)&v1.x) + 1));
        float2 p2 = __half22float2(*(__half2*)&v1.z);
        float2 p3 = __half22float2(*(((__half2*)&v1.z) + 1));
        float acc1 = tanh_approx(p0.x + w0.x) + tanh_approx(p0.y + w0.y) +
                     tanh_approx(p1.x + w0.z) + tanh_approx(p1.y + w0.w) +
                     tanh_approx(p2.x + w1.x) + tanh_approx(p2.y + w1.y) +
                     tanh_approx(p3.x + w1.z) + tanh_approx(p3.y + w1.w);

        float2 q0 = __half22float2(*(__half2*)&v2.x);
        float2 q1 = __half22float2(*(((__half2*)&v2.x) + 1));
        float2 q2 = __half22float2(*(__half2*)&v2.z);
        float2 q3 = __half22float2(*(((__half2*)&v2.z) + 1));
        float acc2 = tanh_approx(q0.x + w0.x) + tanh_approx(q0.y + w0.y) +
                     tanh_approx(q1.x + w0.z) + tanh_approx(q1.y + w0.w) +
                     tanh_approx(q2.x + w1.x) + tanh_approx(q2.y + w1.y) +
                     tanh_approx(q3.x + w1.z) + tanh_approx(q3.y + w1.w);
#pragma unroll
        for (int o = 16; o; o >>= 1) {
            acc1 += __shfl_xor_sync(0xffffffffu, acc1, o);
            acc2 += __shfl_xor_sync(0xffffffffu, acc2, o);
        }
        if (lane == 0) {
            g_esum[b * SS + s1] = acc1;
            g_esum[b * SS + s2] = acc2;
        }
    }
}

// ---------------- per-step softmax + ctx partial: grid (4 s-chunks, 128 b) ----------------
__global__ __launch_bounds__(512) void k_ctx() {
    __shared__ __align__(16) float sh_e[SS];
    __shared__ float sh_red[16];
    __shared__ float sh_sum[16];
    __shared__ __align__(16) float sh_ctxp[16][264];

    int c = blockIdx.x;
    int b = blockIdx.y;
    int tid = threadIdx.x;
    int lane = tid & 31;
    int warp = tid >> 5;

    float e = g_esum[b * SS + tid];

    float m = e;
#pragma unroll
    for (int o = 16; o; o >>= 1) m = fmaxf(m, __shfl_xor_sync(0xffffffffu, m, o));
    if (lane == 0) sh_red[warp] = m;
    __syncthreads();
    float mx = sh_red[0];
#pragma unroll
    for (int i = 1; i < 16; i++) mx = fmaxf(mx, sh_red[i]);
    float w = __expf(e - mx);
    float ws = w;
#pragma unroll
    for (int o = 16; o; o >>= 1) ws += __shfl_xor_sync(0xffffffffu, ws, o);
    if (lane == 0) sh_sum[warp] = ws;
    __syncthreads();
    float total = 0.f;
#pragma unroll
    for (int i = 0; i < 16; i++) total += sh_sum[i];
    float inv = __fdividef(1.f, total);
    sh_e[tid] = w * inv;
    __syncthreads();

    {
        int e8 = tid & 31;
        int sp = tid >> 5;
        const uint4* mb = (const uint4*)(g_memt + (size_t)b * SS * DD);
        float acc[8];
#pragma unroll
        for (int j = 0; j < 8; j++) acc[j] = 0.f;
#pragma unroll
        for (int k = 0; k < 8; k++) {
            int s = c * 128 + sp + k * 16;
            uint4 v = mb[s * 32 + e8];
            float a = sh_e[s];
            float2 f0 = __half22float2(*(__half2*)&v.x);
            float2 f1 = __half22float2(*(((__half2*)&v.x) + 1));
            float2 f2 = __half22float2(*(__half2*)&v.z);
            float2 f3 = __half22float2(*(((__half2*)&v.z) + 1));
            acc[0] = fmaf(a, f0.x, acc[0]);
            acc[1] = fmaf(a, f0.y, acc[1]);
            acc[2] = fmaf(a, f1.x, acc[2]);
            acc[3] = fmaf(a, f1.y, acc[3]);
            acc[4] = fmaf(a, f2.x, acc[4]);
            acc[5] = fmaf(a, f2.y, acc[5]);
            acc[6] = fmaf(a, f3.x, acc[6]);
            acc[7] = fmaf(a, f3.y, acc[7]);
        }
#pragma unroll
        for (int j = 0; j < 8; j++) sh_ctxp[sp][e8 * 8 + j] = acc[j];
    }
    __syncthreads();
    if (tid < DD) {
        float s = 0.f;
#pragma unroll
        for (int i = 0; i < 16; i++) s += sh_ctxp[i][tid];
        g_ctxp[c][b * DD + tid] = s;
    }
}

// ---------------- per-step gate GEMM via HMMA: sources ctx (kz=0) and h (kz=1) ----------------
// gates_partial[kz][b][j] = sum_{k<256} A_src[b][k] * g_w16[j][256 + kz*256 + k]
// grid (32 n-tiles, 4 m-tiles, 2 kz), 128 thr.
__global__ __launch_bounds__(128) void k_gemm(int hp) {
    __shared__ __align__(16) __half sA[32][264];
    __shared__ __align__(16) __half sB[32][264];

    int tid = threadIdx.x;
    int lane = tid & 31;
    int warp = tid >> 5;
    int n0 = blockIdx.x * 32;
    int m0 = blockIdx.y * 32;
    int kz = blockIdx.z;       // 0: ctx, 1: h

    // stage A (float4 vectorized: 512 float4s over 128 thr = 4 iters)
#pragma unroll
    for (int i = 0; i < 4; i++) {
        int idx = tid + i * 128;          // 0..511
        int row = idx >> 4;               // 16 float4 per... (32 rows x 64 float4 = 2048)
        // careful: 32 rows x 256 floats = 2048 float4s -> 16 iters of 128
        (void)row;
    }
    // (corrected loop below)
    {
        const float4* hsrc = (const float4*)g_h[hp];
        const float4* c0p = (const float4*)g_ctxp[0];
        const float4* c1p = (const float4*)g_ctxp[1];
        const float4* c2p = (const float4*)g_ctxp[2];
        const float4* c3p = (const float4*)g_ctxp[3];
#pragma unroll
        for (int i = 0; i < 16; i++) {
            int idx = tid + i * 128;      // 0..2047
            int row = idx >> 6;           // 64 float4 per row
            int c4 = idx & 63;
            int a4 = (m0 + row) * 64 + c4;
            float4 v;
            if (kz == 0) {
                float4 x0 = c0p[a4], x1 = c1p[a4], x2 = c2p[a4], x3 = c3p[a4];
                v.x = (x0.x + x1.x) + (x2.x + x3.x);
                v.y = (x0.y + x1.y) + (x2.y + x3.y);
                v.z = (x0.z + x1.z) + (x2.z + x3.z);
                v.w = (x0.w + x1.w) + (x2.w + x3.w);
            } else {
                v = hsrc[a4];
            }
            *(__half2*)&sA[row][c4 * 4]     = __floats2half2_rn(v.x, v.y);
            *(__half2*)&sA[row][c4 * 4 + 2] = __floats2half2_rn(v.z, v.w);
        }
    }
    // stage B: g_w16 cols 256 + kz*256 .. +255 (uint4 = 8 halves; row offset 32 + kz*32)
    {
        const uint4* wb = (const uint4*)g_w16;
        int coff = 32 + kz * 32;
#pragma unroll
        for (int i = 0; i < 8; i++) {
            int idx = tid + i * 128;
            int row = idx >> 5;
            int c4 = idx & 31;
            uint4 v = wb[(size_t)(n0 + row) * 96 + coff + c4];
            *(uint4*)&sB[row][c4 * 8] = v;
        }
    }
    __syncthreads();

    int g = lane >> 2;
    int tg = lane & 3;
    int mw = (warp >> 1) * 16;
    int nw = (warp & 1) * 16;

    float d0[4] = {0.f, 0.f, 0.f, 0.f};
    float d1[4] = {0.f, 0.f, 0.f, 0.f};

#pragma unroll
    for (int ks = 0; ks < 16; ks++) {
        int kc = ks * 16 + tg * 2;
        uint32_t a0 = *(const uint32_t*)&sA[mw + g][kc];
        uint32_t a1 = *(const uint32_t*)&sA[mw + g + 8][kc];
        uint32_t a2 = *(const uint32_t*)&sA[mw + g][kc + 8];
        uint32_t a3 = *(const uint32_t*)&sA[mw + g + 8][kc + 8];
        uint32_t b0 = *(const uint32_t*)&sB[nw + g][kc];
        uint32_t b1 = *(const uint32_t*)&sB[nw + g][kc + 8];
        uint32_t b2 = *(const uint32_t*)&sB[nw + 8 + g][kc];
        uint32_t b3 = *(const uint32_t*)&sB[nw + 8 + g][kc + 8];

        asm volatile(
            "mma.sync.aligned.m16n8k16.row.col.f32.f16.f16.f32 "
            "{%0,%1,%2,%3}, {%4,%5,%6,%7}, {%8,%9}, {%0,%1,%2,%3};\n"
            : "+f"(d0[0]), "+f"(d0[1]), "+f"(d0[2]), "+f"(d0[3])
            : "r"(a0), "r"(a1), "r"(a2), "r"(a3), "r"(b0), "r"(b1));
        asm volatile(
            "mma.sync.aligned.m16n8k16.row.col.f32.f16.f16.f32 "
            "{%0,%1,%2,%3}, {%4,%5,%6,%7}, {%8,%9}, {%0,%1,%2,%3};\n"
            : "+f"(d1[0]), "+f"(d1[1]), "+f"(d1[2]), "+f"(d1[3])
            : "r"(a0), "r"(a1), "r"(a2), "r"(a3), "r"(b2), "r"(b3));
    }

    {
        int r0 = m0 + mw + g;
        int r1 = r0 + 8;
        int c0 = n0 + nw + tg * 2;
        float* gp = g_gp[kz];
        *(float2*)&gp[(size_t)r0 * GG + c0]     = make_float2(d0[0], d0[1]);
        *(float2*)&gp[(size_t)r1 * GG + c0]     = make_float2(d0[2], d0[3]);
        *(float2*)&gp[(size_t)r0 * GG + c0 + 8] = make_float2(d1[0], d1[1]);
        *(float2*)&gp[(size_t)r1 * GG + c0 + 8] = make_float2(d1[2], d1[3]);
    }
}

// ---------------- final LSTM cell: emits out[TT-1] ----------------
__global__ __launch_bounds__(256) void k_cell_final(const float* __restrict__ b_ih,
                                                    const float* __restrict__ b_hh,
                                                    float* __restrict__ out_t,
                                                    int rp) {
    int idx = blockIdx.x * blockDim.x + threadIdx.x;
    int b = idx >> 8;
    int hd = idx & 255;
    size_t base = (size_t)b * GG;
    size_t pre = ((size_t)(TT - 1) * BB + b) * GG;

    float vi = b_ih[hd] + b_hh[hd] + g_gpre[pre + hd];
    float vf = b_ih[hd + 256] + b_hh[hd + 256] + g_gpre[pre + hd + 256];
    float vg = b_ih[hd + 512] + b_hh[hd + 512] + g_gpre[pre + hd + 512];
    float vo = b_ih[hd + 768] + b_hh[hd + 768] + g_gpre[pre + hd + 768];
#pragma unroll
    for (int p = 0; p < NKZ; p++) {
        vi += g_gp[p][base + hd];
        vf += g_gp[p][base + hd + 256];
        vg += g_gp[p][base + hd + 512];
        vo += g_gp[p][base + hd + 768];
    }

    float gi = fast_sigmoid(vi);
    float gf = fast_sigmoid(vf);
    float gc = fast_tanh(vg);
    float go = fast_sigmoid(vo);
    float c = gf * g_c[rp][idx] + gi * gc;
    float h = go * fast_tanh(c);
    out_t[idx] = h;
}

// ---------------- launch ----------------
// Graph node count: 1 (k_pre) + 1 (k_pregemm) + 255*3 + 1 (final cell) = 768
extern "C" void kernel_launch(void* const* d_in, const int* in_sizes, int n_in,
                              void* d_out, int out_size) {
    const float* tgt    = (const float*)d_in[0];  // (T,B,256)
    const float* memory = (const float*)d_in[1];  // (S,B,256)
    const float* W_attn = (const float*)d_in[2];  // (256,512)
    const float* b_attn = (const float*)d_in[3];  // (256,)
    const float* W_ih   = (const float*)d_in[4];  // (1024,512)
    const float* W_hh   = (const float*)d_in[5];  // (1024,256)
    const float* b_ih   = (const float*)d_in[6];  // (1024,)
    const float* b_hh   = (const float*)d_in[7];  // (1024,)
    float* out = (float*)d_out;                   // (T,B,256)

    (void)in_sizes; (void)n_in; (void)out_size;

    dim3 gmp(4, 1024);
    k_pre<<<gmp, 256>>>(memory, W_attn, b_attn, W_ih, W_hh, out);

    dim3 gpg(32, 1024);
    k_pregemm<<<gpg, 128>>>(tgt);                 // tgt gate partial for all t

    for (int t = 1; t < TT; t++) {
        dim3 ge(4, BB);
        k_energy<<<ge, 512>>>(W_attn, b_ih, b_hh, out + (size_t)(t - 1) * BB * DD, t);
        k_ctx<<<ge, 512>>>();
        dim3 gg(32, 4, NKZ);
        k_gemm<<<gg, 128>>>((t - 1) & 1);
    }
    k_cell_final<<<128, 256>>>(b_ih, b_hh, out + (size_t)(TT - 1) * BB * DD, (TT) & 1);
}